// round 9
// baseline (speedup 1.0000x reference)
#include <cuda_runtime.h>
#include <cuda_fp16.h>
#include <math.h>
#include <stdint.h>

// Problem constants
#define BB   8
#define TT   2048
#define EE   256
#define HH   4
#define HD   64
#define PP   8
#define BT   (BB*TT)          // 16384
#define NBH  (BB*HH)          // 32

// ---------------- scratch (device globals; no allocation allowed) -----------
__device__ float g_h[BT*EE];
__device__ float g_bs[BT];
__device__ float g_weff[EE+1];       // w_eff[256] + b_eff
__device__ float g_zp[HH][BT];       // per-head boundary partials
__device__ float g_chs[BB][32][EE];  // 64-token chunk sums of h
__device__ float g_u[NBH*TT];        // u[bh][t] = v[bh][t] . w_eff_slice(h)
// fp16 hi/lo splits
__device__ __half g_xh[BT*EE], g_xl[BT*EE];
__device__ __half g_hh[BT*EE], g_hl[BT*EE];
__device__ __half g_wsh[4][EE*EE], g_wsl[4][EE*EE];   // w_in, w_q, w_k, w_v
// [bh][t][64] layouts
__device__ __half g_qh[NBH*TT*HD], g_ql[NBH*TT*HD];
__device__ __half g_kh[NBH*TT*HD], g_kl[NBH*TT*HD];

// ============================ warp-mma helpers ==============================
__device__ __forceinline__ uint32_t smem_u32(const void* p) {
    uint32_t a;
    asm("{ .reg .u64 tmp; cvta.to.shared.u64 tmp, %1; cvt.u32.u64 %0, tmp; }"
        : "=r"(a) : "l"(p));
    return a;
}
__device__ __forceinline__ void ldmatrix_x4(uint32_t* r, uint32_t addr) {
    asm volatile("ldmatrix.sync.aligned.m8n8.x4.shared.b16 {%0,%1,%2,%3}, [%4];"
                 : "=r"(r[0]), "=r"(r[1]), "=r"(r[2]), "=r"(r[3]) : "r"(addr));
}
__device__ __forceinline__ void ldmatrix_x2(uint32_t* r, uint32_t addr) {
    asm volatile("ldmatrix.sync.aligned.m8n8.x2.shared.b16 {%0,%1}, [%2];"
                 : "=r"(r[0]), "=r"(r[1]) : "r"(addr));
}
__device__ __forceinline__ void mma16816(float* d, const uint32_t* a, const uint32_t* b) {
    asm volatile(
        "mma.sync.aligned.m16n8k16.row.col.f32.f16.f16.f32 "
        "{%0,%1,%2,%3}, {%4,%5,%6,%7}, {%8,%9}, {%0,%1,%2,%3};"
        : "+f"(d[0]), "+f"(d[1]), "+f"(d[2]), "+f"(d[3])
        : "r"(a[0]), "r"(a[1]), "r"(a[2]), "r"(a[3]), "r"(b[0]), "r"(b[1]));
}
__device__ __forceinline__ uint32_t pack_half2(__half lo, __half hi) {
    return (uint32_t)__half_as_ushort(lo) | ((uint32_t)__half_as_ushort(hi) << 16);
}

// ---------------------------------------------------------------------------
// Fused: x/w_in/w_q/w_k/w_v fp16 hi/lo splits + weff computation.
// Grid layout: [0,4096) x-split | [4096,4352) weight splits | 4352 = weff.
struct SplitArgs {
    const float *x, *w_in, *w_q, *w_k, *w_v, *w_o, *w_bd, *b_o, *b_bd;
};

__device__ __forceinline__ void do_split4(const float* __restrict__ src,
                                          __half* __restrict__ dh,
                                          __half* __restrict__ dl, int i)
{
    float4 v = ((const float4*)src)[i];
    __half h0 = __float2half_rn(v.x), h1 = __float2half_rn(v.y);
    __half h2 = __float2half_rn(v.z), h3 = __float2half_rn(v.w);
    __half l0 = __float2half_rn(v.x - __half2float(h0));
    __half l1 = __float2half_rn(v.y - __half2float(h1));
    __half l2 = __float2half_rn(v.z - __half2float(h2));
    __half l3 = __float2half_rn(v.w - __half2float(h3));
    ((uint2*)dh)[i] = make_uint2(pack_half2(h0, h1), pack_half2(h2, h3));
    ((uint2*)dl)[i] = make_uint2(pack_half2(l0, l1), pack_half2(l2, l3));
}

__global__ __launch_bounds__(256) void split_all(SplitArgs a)
{
    int blk = blockIdx.x;
    int tid = threadIdx.x;
    if (blk < 4096) {
        do_split4(a.x, g_xh, g_xl, blk * 256 + tid);
    } else if (blk < 4352) {
        int w = (blk - 4096) >> 6;            // 0..3
        int i = ((blk - 4096) & 63) * 256 + tid;
        const float* src = (w == 0) ? a.w_in : (w == 1) ? a.w_q : (w == 2) ? a.w_k : a.w_v;
        do_split4(src, g_wsh[w], g_wsl[w], i);
    } else {
        // weff: w_eff[j] = sum_i w_bd[i]*w_o[i][j]; b_eff
        int j = tid;
        float s = 0.f;
        for (int i = 0; i < EE; i++) s += a.w_bd[i] * a.w_o[i * EE + j];
        g_weff[j] = s;
        if (j == 0) {
            float bb = a.b_bd[0];
            for (int i = 0; i < EE; i++) bb += a.w_bd[i] * a.b_o[i];
            g_weff[EE] = bb;
        }
    }
}

// ---------------------------------------------------------------------------
// Tensor-core GEMM: C[m][n] = sum_k A[m][k]*W[n][k] + bias[n], fp16 3-MMA split.
// CTA: 128 threads (4 warps), tile 64(m) x 64(n). Grid: (M/64, 256/64).
// mode 0: fp32 to outf + hi/lo split to oh/ol (row-major [m][256]).
// mode 1: q -> oh/ol at [bh][t][d], scaled by 0.125.
// mode 2: k -> oh/ol at [bh][t][d].
// mode 3: v -> u[bh][t] = (v row) . g_weff slice   (no v materialization)
__global__ __launch_bounds__(128) void gemm_tc(const __half* __restrict__ Ah,
                                               const __half* __restrict__ Al,
                                               const __half* __restrict__ Wh,
                                               const __half* __restrict__ Wl,
                                               const float* __restrict__ bias,
                                               float* __restrict__ outf,
                                               __half* __restrict__ oh,
                                               __half* __restrict__ ol,
                                               int mode)
{
    __shared__ __half Ash[64][72], Asl[64][72], Wsh[64][72], Wsl[64][72];
    const int m0 = blockIdx.x * 64;
    const int n0 = blockIdx.y * 64;
    const int tid = threadIdx.x;
    const int wid = tid >> 5;
    const int lane = tid & 31;
    const int g = lane >> 2, t4 = lane & 3;

    float acc[8][4];
#pragma unroll
    for (int i = 0; i < 8; i++)
#pragma unroll
        for (int j = 0; j < 4; j++) acc[i][j] = 0.f;

    const int arow = 16 * wid + (lane & 15);
    const int asel = (lane & 16) ? 8 : 0;
    const int brow = lane & 7;
    const int bsel = (lane & 8) ? 8 : 0;

    for (int kc0 = 0; kc0 < EE; kc0 += 64) {
        if (kc0) __syncthreads();
#pragma unroll
        for (int j = 0; j < 4; j++) {
            int i = tid + j * 128;            // 0..511
            int r = i >> 3, c = (i & 7) * 8;
            *(uint4*)&Ash[r][c] = *(const uint4*)&Ah[(size_t)(m0 + r) * EE + kc0 + c];
            *(uint4*)&Asl[r][c] = *(const uint4*)&Al[(size_t)(m0 + r) * EE + kc0 + c];
            *(uint4*)&Wsh[r][c] = *(const uint4*)&Wh[(size_t)(n0 + r) * EE + kc0 + c];
            *(uint4*)&Wsl[r][c] = *(const uint4*)&Wl[(size_t)(n0 + r) * EE + kc0 + c];
        }
        __syncthreads();

        uint32_t afh[4][4], afl[4][4];
#pragma unroll
        for (int kc = 0; kc < 4; kc++) {
            ldmatrix_x4(afh[kc], smem_u32(&Ash[arow][kc * 16 + asel]));
            ldmatrix_x4(afl[kc], smem_u32(&Asl[arow][kc * 16 + asel]));
        }
#pragma unroll
        for (int kc = 0; kc < 4; kc++) {
#pragma unroll
            for (int nb = 0; nb < 8; nb++) {
                uint32_t bh2[2], bl2[2];
                ldmatrix_x2(bh2, smem_u32(&Wsh[8 * nb + brow][kc * 16 + bsel]));
                ldmatrix_x2(bl2, smem_u32(&Wsl[8 * nb + brow][kc * 16 + bsel]));
                mma16816(acc[nb], afh[kc], bh2);
                mma16816(acc[nb], afh[kc], bl2);
                mma16816(acc[nb], afl[kc], bh2);
            }
        }
    }

    // epilogue
    const int r0 = m0 + 16 * wid + g;
    const int r1 = r0 + 8;
    if (mode == 0) {
#pragma unroll
        for (int nb = 0; nb < 8; nb++) {
            int c0 = n0 + 8 * nb + 2 * t4;
            float bx = bias[c0], by = bias[c0 + 1];
            float v00 = acc[nb][0] + bx, v01 = acc[nb][1] + by;
            float v10 = acc[nb][2] + bx, v11 = acc[nb][3] + by;
            *(float2*)&outf[(size_t)r0 * EE + c0] = make_float2(v00, v01);
            *(float2*)&outf[(size_t)r1 * EE + c0] = make_float2(v10, v11);
            __half h00 = __float2half_rn(v00), h01 = __float2half_rn(v01);
            __half h10 = __float2half_rn(v10), h11 = __float2half_rn(v11);
            *(uint32_t*)&oh[(size_t)r0 * EE + c0] = pack_half2(h00, h01);
            *(uint32_t*)&oh[(size_t)r1 * EE + c0] = pack_half2(h10, h11);
            *(uint32_t*)&ol[(size_t)r0 * EE + c0] =
                pack_half2(__float2half_rn(v00 - __half2float(h00)),
                           __float2half_rn(v01 - __half2float(h01)));
            *(uint32_t*)&ol[(size_t)r1 * EE + c0] =
                pack_half2(__float2half_rn(v10 - __half2float(h10)),
                           __float2half_rn(v11 - __half2float(h11)));
        }
    } else if (mode == 3) {
        float z0 = 0.f, z1 = 0.f;
#pragma unroll
        for (int nb = 0; nb < 8; nb++) {
            int c0 = n0 + 8 * nb + 2 * t4;
            float bx = bias[c0], by = bias[c0 + 1];
            float wx = g_weff[c0], wy = g_weff[c0 + 1];
            z0 += (acc[nb][0] + bx) * wx + (acc[nb][1] + by) * wy;
            z1 += (acc[nb][2] + bx) * wx + (acc[nb][3] + by) * wy;
        }
#pragma unroll
        for (int m = 1; m <= 2; m <<= 1) {
            z0 += __shfl_xor_sync(0xffffffffu, z0, m);
            z1 += __shfl_xor_sync(0xffffffffu, z1, m);
        }
        if (t4 == 0) {
            int hh = n0 >> 6;
            int b = r0 >> 11, t = r0 & (TT - 1);
            size_t base = (size_t)(b * HH + hh) * TT;
            g_u[base + t] = z0;
            g_u[base + t + 8] = z1;
        }
    } else {
        const float scale = (mode == 1) ? 0.125f : 1.0f;
#pragma unroll
        for (int nb = 0; nb < 8; nb++) {
            int c0 = n0 + 8 * nb + 2 * t4;
            float bx = bias[c0], by = bias[c0 + 1];
            float v00 = (acc[nb][0] + bx) * scale, v01 = (acc[nb][1] + by) * scale;
            float v10 = (acc[nb][2] + bx) * scale, v11 = (acc[nb][3] + by) * scale;
            int hh = c0 >> 6, d = c0 & 63;
            int b = r0 >> 11, t0n = r0 & (TT - 1);
            size_t base = ((size_t)((b * HH + hh) * TT)) * HD + d;
            size_t i0 = base + (size_t)t0n * HD;
            size_t i1 = base + (size_t)(t0n + 8) * HD;
            __half h00 = __float2half_rn(v00), h01 = __float2half_rn(v01);
            __half h10 = __float2half_rn(v10), h11 = __float2half_rn(v11);
            *(uint32_t*)&oh[i0] = pack_half2(h00, h01);
            *(uint32_t*)&oh[i1] = pack_half2(h10, h11);
            *(uint32_t*)&ol[i0] =
                pack_half2(__float2half_rn(v00 - __half2float(h00)),
                           __float2half_rn(v01 - __half2float(h01)));
            *(uint32_t*)&ol[i1] =
                pack_half2(__float2half_rn(v10 - __half2float(h10)),
                           __float2half_rn(v11 - __half2float(h11)));
        }
    }
}

// ---------------------------------------------------------------------------
// 64-token chunk sums of h: g_chs[b][c][d] = sum_{t in chunk} h[b][t][d]
__global__ __launch_bounds__(256) void chs_kernel()
{
    int b = blockIdx.x, c = blockIdx.y, d = threadIdx.x;
    const float* p = g_h + ((size_t)b * TT + c * 64) * EE + d;
    float s = 0.f;
#pragma unroll 8
    for (int i = 0; i < 64; i++) s += p[(size_t)i * EE];
    g_chs[b][c][d] = s;
}

// ---------------------------------------------------------------------------
// Flash attention v3, S-only: z[t] = (sum p*u)/(sum p), p = exp(q.k/8).
// fp16 3-MMA hi/lo split (fp32-accurate). 128 q rows / CTA, 8 warps.
// Double-buffered K stages, one __syncthreads per KV tile.
struct AttnStage {
    __half kh[64][72];
    __half kl[64][72];
};

__global__ __launch_bounds__(256) void attn_mma()
{
    __shared__ AttnStage stg[2];
    __shared__ float us[2][64];
    const int tid = threadIdx.x;
    const int wid = tid >> 5;          // 0..7
    const int lane = tid & 31;
    const int bh = blockIdx.y;
    const int qt0 = blockIdx.x * 128;
    const int b = bh >> 2, hh = bh & 3;
    const int g = lane >> 2, t4 = lane & 3;

    // ---- stage Q (128 rows, hi/lo) through both stages, extract fragments ----
    {
        const uint4* Qh = (const uint4*)(g_qh + ((size_t)bh * TT + qt0) * HD);
        const uint4* Ql = (const uint4*)(g_ql + ((size_t)bh * TT + qt0) * HD);
#pragma unroll
        for (int i = tid; i < 1024; i += 256) {   // 128 rows x 8 chunks
            int r = i >> 3, c8 = i & 7;
            AttnStage* s = &stg[r >> 6];
            int rr = r & 63;
            *(uint4*)&s->kh[rr][c8 * 8] = Qh[i];
            *(uint4*)&s->kl[rr][c8 * 8] = Ql[i];
        }
    }
    __syncthreads();

    uint32_t qfh[4][4], qfl[4][4];
    {
        AttnStage* s = &stg[wid >> 2];
        int arow = 16 * (wid & 3) + (lane & 15);
        int acolsel = (lane & 16) ? 8 : 0;
#pragma unroll
        for (int kc = 0; kc < 4; kc++) {
            ldmatrix_x4(qfh[kc], smem_u32(&s->kh[arow][kc * 16 + acolsel]));
            ldmatrix_x4(qfl[kc], smem_u32(&s->kl[arow][kc * 16 + acolsel]));
        }
    }
    __syncthreads();

    // ---- preload K tile 0 + u[0] into stage 0 ----
    {
        const size_t base = (size_t)bh * TT * HD;
        const uint4* Kh = (const uint4*)(g_kh + base);
        const uint4* Kl = (const uint4*)(g_kl + base);
#pragma unroll
        for (int i = tid; i < 512; i += 256) {
            int r = i >> 3, c8 = i & 7;
            *(uint4*)&stg[0].kh[r][c8 * 8] = Kh[i];
            *(uint4*)&stg[0].kl[r][c8 * 8] = Kl[i];
        }
        if (tid < 16)
            *(float4*)&us[0][tid * 4] = *(const float4*)&g_u[(size_t)bh * TT + tid * 4];
    }
    __syncthreads();

    float lacc0 = 0.f, lacc8 = 0.f, zn0 = 0.f, zn8 = 0.f;

    const int brow4 = ((lane & 16) ? 8 : 0) + (lane & 7);
    const int bsel8 = (lane & 8) ? 8 : 0;

    for (int kt = 0; kt < TT / 64; kt++) {
        const int cur = kt & 1;
        const AttnStage* st = &stg[cur];

        // issue loads of next tile into the idle stage (overlaps with compute)
        if (kt + 1 < TT / 64) {
            const size_t base = ((size_t)bh * TT + (kt + 1) * 64) * HD;
            const uint4* Kh = (const uint4*)(g_kh + base);
            const uint4* Kl = (const uint4*)(g_kl + base);
            AttnStage* ns = &stg[cur ^ 1];
#pragma unroll
            for (int i = tid; i < 512; i += 256) {
                int r = i >> 3, c8 = i & 7;
                *(uint4*)&ns->kh[r][c8 * 8] = Kh[i];
                *(uint4*)&ns->kl[r][c8 * 8] = Kl[i];
            }
            if (tid < 16)
                *(float4*)&us[cur ^ 1][tid * 4] =
                    *(const float4*)&g_u[(size_t)bh * TT + (kt + 1) * 64 + tid * 4];
        }

        // ---- S = Q K^T, 3-way split ----
        float S[8][4];
#pragma unroll
        for (int i = 0; i < 8; i++)
#pragma unroll
            for (int j = 0; j < 4; j++) S[i][j] = 0.f;
#pragma unroll
        for (int kc = 0; kc < 4; kc++) {
#pragma unroll
            for (int nbp = 0; nbp < 4; nbp++) {
                uint32_t bf4[4], bl4[4];
                ldmatrix_x4(bf4, smem_u32(&st->kh[16 * nbp + brow4][16 * kc + bsel8]));
                ldmatrix_x4(bl4, smem_u32(&st->kl[16 * nbp + brow4][16 * kc + bsel8]));
                mma16816(S[2 * nbp],     qfh[kc], bf4);
                mma16816(S[2 * nbp],     qfh[kc], bl4);
                mma16816(S[2 * nbp],     qfl[kc], bf4);
                mma16816(S[2 * nbp + 1], qfh[kc], bf4 + 2);
                mma16816(S[2 * nbp + 1], qfh[kc], bl4 + 2);
                mma16816(S[2 * nbp + 1], qfl[kc], bf4 + 2);
            }
        }

        // ---- p = exp(s); accumulate l and z-numerator ----
#pragma unroll
        for (int nb = 0; nb < 8; nb++) {
            float2 uu = *(const float2*)&us[cur][8 * nb + 2 * t4];
            float p0 = __expf(S[nb][0]);
            float p1 = __expf(S[nb][1]);
            float p2 = __expf(S[nb][2]);
            float p3 = __expf(S[nb][3]);
            lacc0 += p0 + p1;
            lacc8 += p2 + p3;
            zn0 += p0 * uu.x + p1 * uu.y;
            zn8 += p2 * uu.x + p3 * uu.y;
        }
        __syncthreads();
    }

    // reduce across the 4 lanes of each row group
#pragma unroll
    for (int m = 1; m <= 2; m <<= 1) {
        lacc0 += __shfl_xor_sync(0xffffffffu, lacc0, m);
        lacc8 += __shfl_xor_sync(0xffffffffu, lacc8, m);
        zn0 += __shfl_xor_sync(0xffffffffu, zn0, m);
        zn8 += __shfl_xor_sync(0xffffffffu, zn8, m);
    }
    if (t4 == 0) {
        int row = qt0 + 16 * wid + g;
        g_zp[hh][b * TT + row] = zn0 / lacc0;
        g_zp[hh][b * TT + row + 8] = zn8 / lacc8;
    }
}

// ---------------------------------------------------------------------------
// bs[t] = sigmoid(sum_h zp[h][t] + b_eff)
__global__ __launch_bounds__(256) void zsig_kernel()
{
    int t = blockIdx.x * 256 + threadIdx.x;
    float z = g_zp[0][t] + g_zp[1][t] + g_zp[2][t] + g_zp[3][t] + g_weff[EE];
    g_bs[t] = 1.0f / (1.0f + expf(-z));
}

// ---------------------------------------------------------------------------
// Per batch: fp64 cumsum -> pid -> segment means (chunk sums + edges) -> proj
__global__ __launch_bounds__(256) void finalize_kernel(const float* __restrict__ w_pr,
                                                       const float* __restrict__ b_pr,
                                                       float* __restrict__ out)
{
    __shared__ float  sc[TT];
    __shared__ double sd[TT];
    __shared__ double part[256];
    __shared__ unsigned char pids[TT];
    __shared__ int starts[PP + 1];
    __shared__ float pe[PP][EE];

    const int b = blockIdx.x;
    const int tid = threadIdx.x;

    for (int t = tid; t < TT; t += 256) sc[t] = g_bs[b * TT + t];
    __syncthreads();

    {
        double s = 0.0;
#pragma unroll
        for (int i = 0; i < 8; i++) s += (double)sc[tid * 8 + i];
        part[tid] = s;
    }
    __syncthreads();
    if (tid == 0) {
        double run = 0.0;
        for (int i = 0; i < 256; i++) { double v = part[i]; part[i] = run; run += v; }
    }
    __syncthreads();
    {
        double c = part[tid];
#pragma unroll
        for (int i = 0; i < 8; i++) { c += (double)sc[tid * 8 + i]; sd[tid * 8 + i] = c; }
    }
    __syncthreads();

    double total = sd[TT - 1];
    double inv = 1.0 / fmax(total, 1e-6);
    for (int t = tid; t < TT; t += 256) {
        int p = (int)(sd[t] * inv * (double)PP);
        pids[t] = (unsigned char)(p > PP - 1 ? PP - 1 : p);
    }
    __syncthreads();

    if (tid == 0) {
        int cur = pids[0];
        for (int p = 0; p <= cur; p++) starts[p] = 0;
        for (int t = 1; t < TT; t++) {
            int p = pids[t];
            while (cur < p) starts[++cur] = t;
        }
        while (cur < PP) starts[++cur] = TT;
    }
    __syncthreads();

    // segment means via chunk sums + edge tokens; thread owns dim d = tid
    const float* hb = g_h + (size_t)b * TT * EE;
    for (int p = 0; p < PP; p++) {
        int s0 = starts[p], s1 = starts[p + 1];
        float sum = 0.f;
        int cs = (s0 + 63) >> 6, ce = s1 >> 6;
        if (cs <= ce) {
            for (int c = cs; c < ce; c++) sum += g_chs[b][c][tid];
            for (int t = s0; t < cs * 64; t++) sum += hb[(size_t)t * EE + tid];
            for (int t = ce * 64; t < s1; t++) sum += hb[(size_t)t * EE + tid];
        } else {
            for (int t = s0; t < s1; t++) sum += hb[(size_t)t * EE + tid];
        }
        float cnt = (float)(s1 - s0);
        pe[p][tid] = sum / fmaxf(cnt, 1.0f);
    }
    __syncthreads();

    // out[b][p][n] = pe[p].w_pr[n] + b_pr[n]; thread owns n = tid
    float bn = b_pr[tid];
    const float* wrow = w_pr + (size_t)tid * EE;
    for (int p = 0; p < PP; p++) {
        float a0 = 0.f, a1 = 0.f;
#pragma unroll 8
        for (int d = 0; d < EE; d += 2) {
            a0 += pe[p][d]     * wrow[d];
            a1 += pe[p][d + 1] * wrow[d + 1];
        }
        out[(size_t)(b * PP + p) * EE + tid] = bn + a0 + a1;
    }
}

// ---------------------------------------------------------------------------
extern "C" void kernel_launch(void* const* d_in, const int* in_sizes, int n_in,
                              void* d_out, int out_size)
{
    SplitArgs sa;
    sa.x    = (const float*)d_in[0];
    sa.w_in = (const float*)d_in[1];
    const float* b_in = (const float*)d_in[2];
    sa.w_q  = (const float*)d_in[3];
    const float* b_q  = (const float*)d_in[4];
    sa.w_k  = (const float*)d_in[5];
    const float* b_k  = (const float*)d_in[6];
    sa.w_v  = (const float*)d_in[7];
    const float* b_v  = (const float*)d_in[8];
    sa.w_o  = (const float*)d_in[9];
    sa.b_o  = (const float*)d_in[10];
    sa.w_bd = (const float*)d_in[11];
    sa.b_bd = (const float*)d_in[12];
    const float* w_pr = (const float*)d_in[13];
    const float* b_pr = (const float*)d_in[14];
    float* out = (float*)d_out;

    float *ph;
    __half *pxh, *pxl, *phh, *phl, *pwh, *pwl;
    __half *pqh, *pql, *pkh, *pkl;
    cudaGetSymbolAddress((void**)&ph,  g_h);
    cudaGetSymbolAddress((void**)&pxh, g_xh);
    cudaGetSymbolAddress((void**)&pxl, g_xl);
    cudaGetSymbolAddress((void**)&phh, g_hh);
    cudaGetSymbolAddress((void**)&phl, g_hl);
    cudaGetSymbolAddress((void**)&pwh, g_wsh);
    cudaGetSymbolAddress((void**)&pwl, g_wsl);
    cudaGetSymbolAddress((void**)&pqh, g_qh);
    cudaGetSymbolAddress((void**)&pql, g_ql);
    cudaGetSymbolAddress((void**)&pkh, g_kh);
    cudaGetSymbolAddress((void**)&pkl, g_kl);

    // launch 1: all splits + weff
    split_all<<<4353, 256>>>(sa);

    dim3 ggrid(BT / 64, EE / 64);
    // launches 2-5: h, q, k, u
    gemm_tc<<<ggrid, 128>>>(pxh, pxl, pwh + 0*EE*EE, pwl + 0*EE*EE, b_in, ph, phh, phl, 0);
    gemm_tc<<<ggrid, 128>>>(phh, phl, pwh + 1*EE*EE, pwl + 1*EE*EE, b_q, nullptr, pqh, pql, 1);
    gemm_tc<<<ggrid, 128>>>(phh, phl, pwh + 2*EE*EE, pwl + 2*EE*EE, b_k, nullptr, pkh, pkl, 2);
    gemm_tc<<<ggrid, 128>>>(phh, phl, pwh + 3*EE*EE, pwl + 3*EE*EE, b_v, nullptr, nullptr, nullptr, 3);

    // launch 6: attention (profiled by ncu -s 5 -c 1)
    attn_mma<<<dim3(TT / 128, NBH), 256>>>();

    chs_kernel<<<dim3(BB, 32), 256>>>();
    zsig_kernel<<<BT / 256, 256>>>();
    finalize_kernel<<<BB, 256>>>(w_pr, b_pr, out);
}

// round 10
// speedup vs baseline: 1.0662x; 1.0662x over previous
#include <cuda_runtime.h>
#include <cuda_fp16.h>
#include <math.h>
#include <stdint.h>

// Problem constants
#define BB   8
#define TT   2048
#define EE   256
#define HH   4
#define HD   64
#define PP   8
#define BT   (BB*TT)          // 16384
#define NBH  (BB*HH)          // 32

// ---------------- scratch (device globals; no allocation allowed) -----------
__device__ float g_h[BT*EE];
__device__ float g_bs[BT];
__device__ float g_weff[EE+1];       // w_eff[256] + b_eff
__device__ float g_zp[HH][BT];       // per-head boundary partials
__device__ float g_chs[BB][32][EE];  // 64-token chunk sums of h
__device__ float g_u[NBH*TT];        // u[bh][t] = v[bh][t] . w_eff_slice(h)
// fp16 hi/lo splits
__device__ __half g_xh[BT*EE], g_xl[BT*EE];
__device__ __half g_hh[BT*EE], g_hl[BT*EE];
__device__ __half g_wsh[4][EE*EE], g_wsl[4][EE*EE];   // w_in, w_q, w_k, w_v
// [bh][t][64] layouts
__device__ __half g_qh[NBH*TT*HD], g_ql[NBH*TT*HD];
__device__ __half g_kh[NBH*TT*HD], g_kl[NBH*TT*HD];

// ============================ warp-mma helpers ==============================
__device__ __forceinline__ uint32_t smem_u32(const void* p) {
    uint32_t a;
    asm("{ .reg .u64 tmp; cvta.to.shared.u64 tmp, %1; cvt.u32.u64 %0, tmp; }"
        : "=r"(a) : "l"(p));
    return a;
}
__device__ __forceinline__ void ldmatrix_x4(uint32_t* r, uint32_t addr) {
    asm volatile("ldmatrix.sync.aligned.m8n8.x4.shared.b16 {%0,%1,%2,%3}, [%4];"
                 : "=r"(r[0]), "=r"(r[1]), "=r"(r[2]), "=r"(r[3]) : "r"(addr));
}
__device__ __forceinline__ void ldmatrix_x2(uint32_t* r, uint32_t addr) {
    asm volatile("ldmatrix.sync.aligned.m8n8.x2.shared.b16 {%0,%1}, [%2];"
                 : "=r"(r[0]), "=r"(r[1]) : "r"(addr));
}
__device__ __forceinline__ void mma16816(float* d, const uint32_t* a, const uint32_t* b) {
    asm volatile(
        "mma.sync.aligned.m16n8k16.row.col.f32.f16.f16.f32 "
        "{%0,%1,%2,%3}, {%4,%5,%6,%7}, {%8,%9}, {%0,%1,%2,%3};"
        : "+f"(d[0]), "+f"(d[1]), "+f"(d[2]), "+f"(d[3])
        : "r"(a[0]), "r"(a[1]), "r"(a[2]), "r"(a[3]), "r"(b[0]), "r"(b[1]));
}
__device__ __forceinline__ uint32_t pack_half2(__half lo, __half hi) {
    return (uint32_t)__half_as_ushort(lo) | ((uint32_t)__half_as_ushort(hi) << 16);
}

// ---------------------------------------------------------------------------
// Fused: x/w_in/w_q/w_k/w_v fp16 hi/lo splits + weff computation.
struct SplitArgs {
    const float *x, *w_in, *w_q, *w_k, *w_v, *w_o, *w_bd, *b_o, *b_bd;
};

__device__ __forceinline__ void do_split4(const float* __restrict__ src,
                                          __half* __restrict__ dh,
                                          __half* __restrict__ dl, int i)
{
    float4 v = ((const float4*)src)[i];
    __half h0 = __float2half_rn(v.x), h1 = __float2half_rn(v.y);
    __half h2 = __float2half_rn(v.z), h3 = __float2half_rn(v.w);
    __half l0 = __float2half_rn(v.x - __half2float(h0));
    __half l1 = __float2half_rn(v.y - __half2float(h1));
    __half l2 = __float2half_rn(v.z - __half2float(h2));
    __half l3 = __float2half_rn(v.w - __half2float(h3));
    ((uint2*)dh)[i] = make_uint2(pack_half2(h0, h1), pack_half2(h2, h3));
    ((uint2*)dl)[i] = make_uint2(pack_half2(l0, l1), pack_half2(l2, l3));
}

__global__ __launch_bounds__(256) void split_all(SplitArgs a)
{
    int blk = blockIdx.x;
    int tid = threadIdx.x;
    if (blk < 4096) {
        do_split4(a.x, g_xh, g_xl, blk * 256 + tid);
    } else if (blk < 4352) {
        int w = (blk - 4096) >> 6;            // 0..3
        int i = ((blk - 4096) & 63) * 256 + tid;
        const float* src = (w == 0) ? a.w_in : (w == 1) ? a.w_q : (w == 2) ? a.w_k : a.w_v;
        do_split4(src, g_wsh[w], g_wsl[w], i);
    } else {
        int j = tid;
        float s = 0.f;
        for (int i = 0; i < EE; i++) s += a.w_bd[i] * a.w_o[i * EE + j];
        g_weff[j] = s;
        if (j == 0) {
            float bb = a.b_bd[0];
            for (int i = 0; i < EE; i++) bb += a.w_bd[i] * a.b_o[i];
            g_weff[EE] = bb;
        }
    }
}

// ---------------------------------------------------------------------------
// Shared GEMM mainloop: acc[8][4] += A[64,k] W^T tile, fp16 3-MMA split.
// CTA: 128 threads (4 warps), tile 64(m) x 64(n).
__device__ __forceinline__ void gemm_core(const __half* __restrict__ Ah,
                                          const __half* __restrict__ Al,
                                          const __half* __restrict__ Wh,
                                          const __half* __restrict__ Wl,
                                          __half (*Ash)[72], __half (*Asl)[72],
                                          __half (*Wsh)[72], __half (*Wsl)[72],
                                          int m0, int n0, int tid,
                                          float acc[8][4])
{
    const int wid = tid >> 5;
    const int lane = tid & 31;
    const int arow = 16 * wid + (lane & 15);
    const int asel = (lane & 16) ? 8 : 0;
    const int brow = lane & 7;
    const int bsel = (lane & 8) ? 8 : 0;

    for (int kc0 = 0; kc0 < EE; kc0 += 64) {
        if (kc0) __syncthreads();
#pragma unroll
        for (int j = 0; j < 4; j++) {
            int i = tid + j * 128;            // 0..511
            int r = i >> 3, c = (i & 7) * 8;
            *(uint4*)&Ash[r][c] = *(const uint4*)&Ah[(size_t)(m0 + r) * EE + kc0 + c];
            *(uint4*)&Asl[r][c] = *(const uint4*)&Al[(size_t)(m0 + r) * EE + kc0 + c];
            *(uint4*)&Wsh[r][c] = *(const uint4*)&Wh[(size_t)(n0 + r) * EE + kc0 + c];
            *(uint4*)&Wsl[r][c] = *(const uint4*)&Wl[(size_t)(n0 + r) * EE + kc0 + c];
        }
        __syncthreads();

        uint32_t afh[4][4], afl[4][4];
#pragma unroll
        for (int kc = 0; kc < 4; kc++) {
            ldmatrix_x4(afh[kc], smem_u32(&Ash[arow][kc * 16 + asel]));
            ldmatrix_x4(afl[kc], smem_u32(&Asl[arow][kc * 16 + asel]));
        }
#pragma unroll
        for (int kc = 0; kc < 4; kc++) {
#pragma unroll
            for (int nb = 0; nb < 8; nb++) {
                uint32_t bh2[2], bl2[2];
                ldmatrix_x2(bh2, smem_u32(&Wsh[8 * nb + brow][kc * 16 + bsel]));
                ldmatrix_x2(bl2, smem_u32(&Wsl[8 * nb + brow][kc * 16 + bsel]));
                mma16816(acc[nb], afh[kc], bh2);
                mma16816(acc[nb], afh[kc], bl2);
                mma16816(acc[nb], afl[kc], bh2);
            }
        }
    }
}

// h = x @ w_in^T + b_in: fp32 out + hi/lo split, row-major [m][256]
__global__ __launch_bounds__(128) void gemm_h(const float* __restrict__ bias)
{
    __shared__ __half Ash[64][72], Asl[64][72], Wsh[64][72], Wsl[64][72];
    const int m0 = blockIdx.x * 64, n0 = blockIdx.y * 64;
    const int tid = threadIdx.x;
    const int wid = tid >> 5, lane = tid & 31;
    const int g = lane >> 2, t4 = lane & 3;

    float acc[8][4];
#pragma unroll
    for (int i = 0; i < 8; i++)
#pragma unroll
        for (int j = 0; j < 4; j++) acc[i][j] = 0.f;

    gemm_core(g_xh, g_xl, g_wsh[0], g_wsl[0], Ash, Asl, Wsh, Wsl, m0, n0, tid, acc);

    const int r0 = m0 + 16 * wid + g;
    const int r1 = r0 + 8;
#pragma unroll
    for (int nb = 0; nb < 8; nb++) {
        int c0 = n0 + 8 * nb + 2 * t4;
        float bx = bias[c0], by = bias[c0 + 1];
        float v00 = acc[nb][0] + bx, v01 = acc[nb][1] + by;
        float v10 = acc[nb][2] + bx, v11 = acc[nb][3] + by;
        *(float2*)&g_h[(size_t)r0 * EE + c0] = make_float2(v00, v01);
        *(float2*)&g_h[(size_t)r1 * EE + c0] = make_float2(v10, v11);
        __half h00 = __float2half_rn(v00), h01 = __float2half_rn(v01);
        __half h10 = __float2half_rn(v10), h11 = __float2half_rn(v11);
        *(uint32_t*)&g_hh[(size_t)r0 * EE + c0] = pack_half2(h00, h01);
        *(uint32_t*)&g_hh[(size_t)r1 * EE + c0] = pack_half2(h10, h11);
        *(uint32_t*)&g_hl[(size_t)r0 * EE + c0] =
            pack_half2(__float2half_rn(v00 - __half2float(h00)),
                       __float2half_rn(v01 - __half2float(h01)));
        *(uint32_t*)&g_hl[(size_t)r1 * EE + c0] =
            pack_half2(__float2half_rn(v10 - __half2float(h10)),
                       __float2half_rn(v11 - __half2float(h11)));
    }
}

// q (z=0, scale 0.125) and k (z=1) in one launch; out [bh][t][d] hi/lo.
__global__ __launch_bounds__(128) void gemm_qk(const float* __restrict__ bias_q,
                                               const float* __restrict__ bias_k)
{
    __shared__ __half Ash[64][72], Asl[64][72], Wsh[64][72], Wsl[64][72];
    const int m0 = blockIdx.x * 64, n0 = blockIdx.y * 64;
    const int z = blockIdx.z;
    const int tid = threadIdx.x;
    const int wid = tid >> 5, lane = tid & 31;
    const int g = lane >> 2, t4 = lane & 3;

    const __half* Wh = z ? g_wsh[2] : g_wsh[1];
    const __half* Wl = z ? g_wsl[2] : g_wsl[1];
    const float* bias = z ? bias_k : bias_q;
    __half* oh = z ? g_kh : g_qh;
    __half* ol = z ? g_kl : g_ql;
    const float scale = z ? 1.0f : 0.125f;

    float acc[8][4];
#pragma unroll
    for (int i = 0; i < 8; i++)
#pragma unroll
        for (int j = 0; j < 4; j++) acc[i][j] = 0.f;

    gemm_core(g_hh, g_hl, Wh, Wl, Ash, Asl, Wsh, Wsl, m0, n0, tid, acc);

    const int r0 = m0 + 16 * wid + g;
#pragma unroll
    for (int nb = 0; nb < 8; nb++) {
        int c0 = n0 + 8 * nb + 2 * t4;
        float bx = bias[c0], by = bias[c0 + 1];
        float v00 = (acc[nb][0] + bx) * scale, v01 = (acc[nb][1] + by) * scale;
        float v10 = (acc[nb][2] + bx) * scale, v11 = (acc[nb][3] + by) * scale;
        int hh = c0 >> 6, d = c0 & 63;
        int b = r0 >> 11, t0n = r0 & (TT - 1);
        size_t base = ((size_t)((b * HH + hh) * TT)) * HD + d;
        size_t i0 = base + (size_t)t0n * HD;
        size_t i1 = base + (size_t)(t0n + 8) * HD;
        __half h00 = __float2half_rn(v00), h01 = __float2half_rn(v01);
        __half h10 = __float2half_rn(v10), h11 = __float2half_rn(v11);
        *(uint32_t*)&oh[i0] = pack_half2(h00, h01);
        *(uint32_t*)&oh[i1] = pack_half2(h10, h11);
        *(uint32_t*)&ol[i0] =
            pack_half2(__float2half_rn(v00 - __half2float(h00)),
                       __float2half_rn(v01 - __half2float(h01)));
        *(uint32_t*)&ol[i1] =
            pack_half2(__float2half_rn(v10 - __half2float(h10)),
                       __float2half_rn(v11 - __half2float(h11)));
    }
}

// u[bh][t] = (v row) . g_weff slice (v never materialized)
__global__ __launch_bounds__(128) void gemm_u(const float* __restrict__ bias)
{
    __shared__ __half Ash[64][72], Asl[64][72], Wsh[64][72], Wsl[64][72];
    const int m0 = blockIdx.x * 64, n0 = blockIdx.y * 64;
    const int tid = threadIdx.x;
    const int wid = tid >> 5, lane = tid & 31;
    const int g = lane >> 2, t4 = lane & 3;

    float acc[8][4];
#pragma unroll
    for (int i = 0; i < 8; i++)
#pragma unroll
        for (int j = 0; j < 4; j++) acc[i][j] = 0.f;

    gemm_core(g_hh, g_hl, g_wsh[3], g_wsl[3], Ash, Asl, Wsh, Wsl, m0, n0, tid, acc);

    const int r0 = m0 + 16 * wid + g;
    float z0 = 0.f, z1 = 0.f;
#pragma unroll
    for (int nb = 0; nb < 8; nb++) {
        int c0 = n0 + 8 * nb + 2 * t4;
        float bx = bias[c0], by = bias[c0 + 1];
        float wx = g_weff[c0], wy = g_weff[c0 + 1];
        z0 += (acc[nb][0] + bx) * wx + (acc[nb][1] + by) * wy;
        z1 += (acc[nb][2] + bx) * wx + (acc[nb][3] + by) * wy;
    }
#pragma unroll
    for (int m = 1; m <= 2; m <<= 1) {
        z0 += __shfl_xor_sync(0xffffffffu, z0, m);
        z1 += __shfl_xor_sync(0xffffffffu, z1, m);
    }
    if (t4 == 0) {
        int hh = n0 >> 6;
        int b = r0 >> 11, t = r0 & (TT - 1);
        size_t base = (size_t)(b * HH + hh) * TT;
        g_u[base + t] = z0;
        g_u[base + t + 8] = z1;
    }
}

// ---------------------------------------------------------------------------
// 64-token chunk sums of h: g_chs[b][c][d] = sum_{t in chunk} h[b][t][d]
__global__ __launch_bounds__(256) void chs_kernel()
{
    int b = blockIdx.x, c = blockIdx.y, d = threadIdx.x;
    const float* p = g_h + ((size_t)b * TT + c * 64) * EE + d;
    float s = 0.f;
#pragma unroll 8
    for (int i = 0; i < 64; i++) s += p[(size_t)i * EE];
    g_chs[b][c][d] = s;
}

// ---------------------------------------------------------------------------
// Flash attention, S-only (R8 shape): z[t] = (sum p*u)/(sum p), p = exp(q.k/8).
// fp16 3-MMA hi/lo split (fp32-accurate). CTA: 128 threads (4 warps), 64 q rows.
struct AttnSmem {
    __half kh[64][72];
    __half kl[64][72];
    float u[64];
};

__global__ __launch_bounds__(128) void attn_mma()
{
    __shared__ AttnSmem sm;
    const int tid = threadIdx.x;
    const int wid = tid >> 5;
    const int lane = tid & 31;
    const int bh = blockIdx.y;
    const int qt0 = blockIdx.x * 64;
    const int b = bh >> 2, hh = bh & 3;
    const int g = lane >> 2, t4 = lane & 3;

    // ---- stage Q (hi/lo) into kh/kl, extract A-fragments ----
    {
        const uint4* Qh = (const uint4*)(g_qh + ((size_t)bh * TT + qt0) * HD);
        const uint4* Ql = (const uint4*)(g_ql + ((size_t)bh * TT + qt0) * HD);
#pragma unroll
        for (int i = tid; i < 512; i += 128) {
            int r = i >> 3, c8 = i & 7;
            *(uint4*)&sm.kh[r][c8 * 8] = Qh[i];
            *(uint4*)&sm.kl[r][c8 * 8] = Ql[i];
        }
    }
    __syncthreads();

    uint32_t qfh[4][4], qfl[4][4];
    {
        int arow = 16 * wid + (lane & 15);
        int acolsel = (lane & 16) ? 8 : 0;
#pragma unroll
        for (int kc = 0; kc < 4; kc++) {
            ldmatrix_x4(qfh[kc], smem_u32(&sm.kh[arow][kc * 16 + acolsel]));
            ldmatrix_x4(qfl[kc], smem_u32(&sm.kl[arow][kc * 16 + acolsel]));
        }
    }
    __syncthreads();

    float lacc0 = 0.f, lacc8 = 0.f, zn0 = 0.f, zn8 = 0.f;

    const int brow4 = ((lane & 16) ? 8 : 0) + (lane & 7);
    const int bsel8 = (lane & 8) ? 8 : 0;

    for (int kt = 0; kt < TT / 64; kt++) {
        // ---- load K tile (hi/lo) + u segment ----
        {
            const size_t base = ((size_t)bh * TT + kt * 64) * HD;
            const uint4* Kh = (const uint4*)(g_kh + base);
            const uint4* Kl = (const uint4*)(g_kl + base);
#pragma unroll
            for (int i = tid; i < 512; i += 128) {
                int r = i >> 3, c8 = i & 7;
                *(uint4*)&sm.kh[r][c8 * 8] = Kh[i];
                *(uint4*)&sm.kl[r][c8 * 8] = Kl[i];
            }
            if (tid < 16)
                *(float4*)&sm.u[tid * 4] =
                    *(const float4*)&g_u[(size_t)bh * TT + kt * 64 + tid * 4];
        }
        __syncthreads();

        // ---- S = Q K^T, 3-way split, x4 B-loads over nb pairs ----
        float S[8][4];
#pragma unroll
        for (int i = 0; i < 8; i++)
#pragma unroll
            for (int j = 0; j < 4; j++) S[i][j] = 0.f;
#pragma unroll
        for (int kc = 0; kc < 4; kc++) {
#pragma unroll
            for (int nbp = 0; nbp < 4; nbp++) {
                uint32_t bf4[4], bl4[4];
                ldmatrix_x4(bf4, smem_u32(&sm.kh[16 * nbp + brow4][16 * kc + bsel8]));
                ldmatrix_x4(bl4, smem_u32(&sm.kl[16 * nbp + brow4][16 * kc + bsel8]));
                mma16816(S[2 * nbp],     qfh[kc], bf4);
                mma16816(S[2 * nbp],     qfh[kc], bl4);
                mma16816(S[2 * nbp],     qfl[kc], bf4);
                mma16816(S[2 * nbp + 1], qfh[kc], bf4 + 2);
                mma16816(S[2 * nbp + 1], qfh[kc], bl4 + 2);
                mma16816(S[2 * nbp + 1], qfl[kc], bf4 + 2);
            }
        }

        // ---- p = exp(s); accumulate l and z-numerator ----
#pragma unroll
        for (int nb = 0; nb < 8; nb++) {
            float2 uu = *(const float2*)&sm.u[8 * nb + 2 * t4];
            float p0 = __expf(S[nb][0]);
            float p1 = __expf(S[nb][1]);
            float p2 = __expf(S[nb][2]);
            float p3 = __expf(S[nb][3]);
            lacc0 += p0 + p1;
            lacc8 += p2 + p3;
            zn0 += p0 * uu.x + p1 * uu.y;
            zn8 += p2 * uu.x + p3 * uu.y;
        }
        __syncthreads();
    }

    // reduce across the 4 lanes of each row group
#pragma unroll
    for (int m = 1; m <= 2; m <<= 1) {
        lacc0 += __shfl_xor_sync(0xffffffffu, lacc0, m);
        lacc8 += __shfl_xor_sync(0xffffffffu, lacc8, m);
        zn0 += __shfl_xor_sync(0xffffffffu, zn0, m);
        zn8 += __shfl_xor_sync(0xffffffffu, zn8, m);
    }
    if (t4 == 0) {
        int row = qt0 + 16 * wid + g;
        g_zp[hh][b * TT + row] = zn0 / lacc0;
        g_zp[hh][b * TT + row + 8] = zn8 / lacc8;
    }
}

// ---------------------------------------------------------------------------
// bs[t] = sigmoid(sum_h zp[h][t] + b_eff)
__global__ __launch_bounds__(256) void zsig_kernel()
{
    int t = blockIdx.x * 256 + threadIdx.x;
    float z = g_zp[0][t] + g_zp[1][t] + g_zp[2][t] + g_zp[3][t] + g_weff[EE];
    g_bs[t] = 1.0f / (1.0f + expf(-z));
}

// ---------------------------------------------------------------------------
// Per batch: fp64 cumsum -> pid -> segment means (chunk sums + edges) -> proj
__global__ __launch_bounds__(256) void finalize_kernel(const float* __restrict__ w_pr,
                                                       const float* __restrict__ b_pr,
                                                       float* __restrict__ out)
{
    __shared__ float  sc[TT];
    __shared__ double sd[TT];
    __shared__ double part[256];
    __shared__ unsigned char pids[TT];
    __shared__ int starts[PP + 1];
    __shared__ float pe[PP][EE];

    const int b = blockIdx.x;
    const int tid = threadIdx.x;

    for (int t = tid; t < TT; t += 256) sc[t] = g_bs[b * TT + t];
    __syncthreads();

    {
        double s = 0.0;
#pragma unroll
        for (int i = 0; i < 8; i++) s += (double)sc[tid * 8 + i];
        part[tid] = s;
    }
    __syncthreads();
    if (tid == 0) {
        double run = 0.0;
        for (int i = 0; i < 256; i++) { double v = part[i]; part[i] = run; run += v; }
    }
    __syncthreads();
    {
        double c = part[tid];
#pragma unroll
        for (int i = 0; i < 8; i++) { c += (double)sc[tid * 8 + i]; sd[tid * 8 + i] = c; }
    }
    __syncthreads();

    double total = sd[TT - 1];
    double inv = 1.0 / fmax(total, 1e-6);
    for (int t = tid; t < TT; t += 256) {
        int p = (int)(sd[t] * inv * (double)PP);
        pids[t] = (unsigned char)(p > PP - 1 ? PP - 1 : p);
    }
    __syncthreads();

    if (tid == 0) {
        int cur = pids[0];
        for (int p = 0; p <= cur; p++) starts[p] = 0;
        for (int t = 1; t < TT; t++) {
            int p = pids[t];
            while (cur < p) starts[++cur] = t;
        }
        while (cur < PP) starts[++cur] = TT;
    }
    __syncthreads();

    // segment means via chunk sums + edge tokens; thread owns dim d = tid
    const float* hb = g_h + (size_t)b * TT * EE;
    for (int p = 0; p < PP; p++) {
        int s0 = starts[p], s1 = starts[p + 1];
        float sum = 0.f;
        int cs = (s0 + 63) >> 6, ce = s1 >> 6;
        if (cs <= ce) {
            for (int c = cs; c < ce; c++) sum += g_chs[b][c][tid];
            for (int t = s0; t < cs * 64; t++) sum += hb[(size_t)t * EE + tid];
            for (int t = ce * 64; t < s1; t++) sum += hb[(size_t)t * EE + tid];
        } else {
            for (int t = s0; t < s1; t++) sum += hb[(size_t)t * EE + tid];
        }
        float cnt = (float)(s1 - s0);
        pe[p][tid] = sum / fmaxf(cnt, 1.0f);
    }
    __syncthreads();

    // out[b][p][n] = pe[p].w_pr[n] + b_pr[n]; thread owns n = tid
    float bn = b_pr[tid];
    const float* wrow = w_pr + (size_t)tid * EE;
    for (int p = 0; p < PP; p++) {
        float a0 = 0.f, a1 = 0.f;
#pragma unroll 8
        for (int d = 0; d < EE; d += 2) {
            a0 += pe[p][d]     * wrow[d];
            a1 += pe[p][d + 1] * wrow[d + 1];
        }
        out[(size_t)(b * PP + p) * EE + tid] = bn + a0 + a1;
    }
}

// ---------------------------------------------------------------------------
extern "C" void kernel_launch(void* const* d_in, const int* in_sizes, int n_in,
                              void* d_out, int out_size)
{
    SplitArgs sa;
    sa.x    = (const float*)d_in[0];
    sa.w_in = (const float*)d_in[1];
    const float* b_in = (const float*)d_in[2];
    sa.w_q  = (const float*)d_in[3];
    const float* b_q  = (const float*)d_in[4];
    sa.w_k  = (const float*)d_in[5];
    const float* b_k  = (const float*)d_in[6];
    sa.w_v  = (const float*)d_in[7];
    const float* b_v  = (const float*)d_in[8];
    sa.w_o  = (const float*)d_in[9];
    sa.b_o  = (const float*)d_in[10];
    sa.w_bd = (const float*)d_in[11];
    sa.b_bd = (const float*)d_in[12];
    const float* w_pr = (const float*)d_in[13];
    const float* b_pr = (const float*)d_in[14];
    float* out = (float*)d_out;

    // launch 1: all splits + weff
    split_all<<<4353, 256>>>(sa);

    dim3 ggrid(BT / 64, EE / 64);
    // launch 2: h
    gemm_h<<<ggrid, 128>>>(b_in);
    // launch 3: q + k fused via grid.z
    gemm_qk<<<dim3(BT / 64, EE / 64, 2), 128>>>(b_q, b_k);
    // launch 4: u
    gemm_u<<<ggrid, 128>>>(b_v);

    // launch 5: attention (ncu capture slot)
    attn_mma<<<dim3(TT / 64, NBH), 128>>>();

    chs_kernel<<<dim3(BB, 32), 256>>>();
    zsig_kernel<<<BT / 256, 256>>>();
    finalize_kernel<<<BB, 256>>>(w_pr, b_pr, out);
}

// round 11
// speedup vs baseline: 1.0712x; 1.0046x over previous
#include <cuda_runtime.h>
#include <cuda_fp16.h>
#include <math.h>
#include <stdint.h>

// Problem constants
#define BB   8
#define TT   2048
#define EE   256
#define HH   4
#define HD   64
#define PP   8
#define BT   (BB*TT)          // 16384
#define NBH  (BB*HH)          // 32

// ---------------- scratch (device globals; no allocation allowed) -----------
__device__ float g_h[BT*EE];
__device__ float g_bs[BT];
__device__ float g_weff[EE+1];       // w_eff[256] + b_eff
__device__ float g_zp[HH][BT];       // per-head boundary partials
__device__ float g_chs[BB][32][EE];  // 64-token chunk sums of h
__device__ float g_u[NBH*TT];        // u[bh][t] = v[bh][t] . w_eff_slice(h)
// fp16 hi/lo splits
__device__ __half g_xh[BT*EE], g_xl[BT*EE];
__device__ __half g_hh[BT*EE], g_hl[BT*EE];
__device__ __half g_wsh[4][EE*EE], g_wsl[4][EE*EE];   // w_in, w_q, w_k, w_v
// [bh][t][64] layouts
__device__ __half g_qh[NBH*TT*HD], g_ql[NBH*TT*HD];
__device__ __half g_kh[NBH*TT*HD], g_kl[NBH*TT*HD];

// ============================ warp-mma helpers ==============================
__device__ __forceinline__ uint32_t smem_u32(const void* p) {
    uint32_t a;
    asm("{ .reg .u64 tmp; cvta.to.shared.u64 tmp, %1; cvt.u32.u64 %0, tmp; }"
        : "=r"(a) : "l"(p));
    return a;
}
__device__ __forceinline__ void ldmatrix_x4(uint32_t* r, uint32_t addr) {
    asm volatile("ldmatrix.sync.aligned.m8n8.x4.shared.b16 {%0,%1,%2,%3}, [%4];"
                 : "=r"(r[0]), "=r"(r[1]), "=r"(r[2]), "=r"(r[3]) : "r"(addr));
}
__device__ __forceinline__ void ldmatrix_x2(uint32_t* r, uint32_t addr) {
    asm volatile("ldmatrix.sync.aligned.m8n8.x2.shared.b16 {%0,%1}, [%2];"
                 : "=r"(r[0]), "=r"(r[1]) : "r"(addr));
}
__device__ __forceinline__ void mma16816(float* d, const uint32_t* a, const uint32_t* b) {
    asm volatile(
        "mma.sync.aligned.m16n8k16.row.col.f32.f16.f16.f32 "
        "{%0,%1,%2,%3}, {%4,%5,%6,%7}, {%8,%9}, {%0,%1,%2,%3};"
        : "+f"(d[0]), "+f"(d[1]), "+f"(d[2]), "+f"(d[3])
        : "r"(a[0]), "r"(a[1]), "r"(a[2]), "r"(a[3]), "r"(b[0]), "r"(b[1]));
}
__device__ __forceinline__ uint32_t pack_half2(__half lo, __half hi) {
    return (uint32_t)__half_as_ushort(lo) | ((uint32_t)__half_as_ushort(hi) << 16);
}

// ---------------------------------------------------------------------------
// Fused: x/w_in/w_q/w_k/w_v fp16 hi/lo splits + weff computation.
struct SplitArgs {
    const float *x, *w_in, *w_q, *w_k, *w_v, *w_o, *w_bd, *b_o, *b_bd;
};

__device__ __forceinline__ void do_split4(const float* __restrict__ src,
                                          __half* __restrict__ dh,
                                          __half* __restrict__ dl, int i)
{
    float4 v = ((const float4*)src)[i];
    __half h0 = __float2half_rn(v.x), h1 = __float2half_rn(v.y);
    __half h2 = __float2half_rn(v.z), h3 = __float2half_rn(v.w);
    __half l0 = __float2half_rn(v.x - __half2float(h0));
    __half l1 = __float2half_rn(v.y - __half2float(h1));
    __half l2 = __float2half_rn(v.z - __half2float(h2));
    __half l3 = __float2half_rn(v.w - __half2float(h3));
    ((uint2*)dh)[i] = make_uint2(pack_half2(h0, h1), pack_half2(h2, h3));
    ((uint2*)dl)[i] = make_uint2(pack_half2(l0, l1), pack_half2(l2, l3));
}

__global__ __launch_bounds__(256) void split_all(SplitArgs a)
{
    int blk = blockIdx.x;
    int tid = threadIdx.x;
    if (blk < 4096) {
        do_split4(a.x, g_xh, g_xl, blk * 256 + tid);
    } else if (blk < 4352) {
        int w = (blk - 4096) >> 6;            // 0..3
        int i = ((blk - 4096) & 63) * 256 + tid;
        const float* src = (w == 0) ? a.w_in : (w == 1) ? a.w_q : (w == 2) ? a.w_k : a.w_v;
        do_split4(src, g_wsh[w], g_wsl[w], i);
    } else {
        int j = tid;
        float s = 0.f;
        for (int i = 0; i < EE; i++) s += a.w_bd[i] * a.w_o[i * EE + j];
        g_weff[j] = s;
        if (j == 0) {
            float bb = a.b_bd[0];
            for (int i = 0; i < EE; i++) bb += a.w_bd[i] * a.b_o[i];
            g_weff[EE] = bb;
        }
    }
}

// ---------------------------------------------------------------------------
// Shared GEMM mainloop: acc[8][4] += A[64,k] W^T tile, fp16 3-MMA split.
// CTA: 128 threads (4 warps), tile 64(m) x 64(n).
__device__ __forceinline__ void gemm_core(const __half* __restrict__ Ah,
                                          const __half* __restrict__ Al,
                                          const __half* __restrict__ Wh,
                                          const __half* __restrict__ Wl,
                                          __half (*Ash)[72], __half (*Asl)[72],
                                          __half (*Wsh)[72], __half (*Wsl)[72],
                                          int m0, int n0, int tid,
                                          float acc[8][4])
{
    const int wid = tid >> 5;
    const int lane = tid & 31;
    const int arow = 16 * wid + (lane & 15);
    const int asel = (lane & 16) ? 8 : 0;
    const int brow = lane & 7;
    const int bsel = (lane & 8) ? 8 : 0;

    for (int kc0 = 0; kc0 < EE; kc0 += 64) {
        if (kc0) __syncthreads();
#pragma unroll
        for (int j = 0; j < 4; j++) {
            int i = tid + j * 128;            // 0..511
            int r = i >> 3, c = (i & 7) * 8;
            *(uint4*)&Ash[r][c] = *(const uint4*)&Ah[(size_t)(m0 + r) * EE + kc0 + c];
            *(uint4*)&Asl[r][c] = *(const uint4*)&Al[(size_t)(m0 + r) * EE + kc0 + c];
            *(uint4*)&Wsh[r][c] = *(const uint4*)&Wh[(size_t)(n0 + r) * EE + kc0 + c];
            *(uint4*)&Wsl[r][c] = *(const uint4*)&Wl[(size_t)(n0 + r) * EE + kc0 + c];
        }
        __syncthreads();

        uint32_t afh[4][4], afl[4][4];
#pragma unroll
        for (int kc = 0; kc < 4; kc++) {
            ldmatrix_x4(afh[kc], smem_u32(&Ash[arow][kc * 16 + asel]));
            ldmatrix_x4(afl[kc], smem_u32(&Asl[arow][kc * 16 + asel]));
        }
#pragma unroll
        for (int kc = 0; kc < 4; kc++) {
#pragma unroll
            for (int nb = 0; nb < 8; nb++) {
                uint32_t bh2[2], bl2[2];
                ldmatrix_x2(bh2, smem_u32(&Wsh[8 * nb + brow][kc * 16 + bsel]));
                ldmatrix_x2(bl2, smem_u32(&Wsl[8 * nb + brow][kc * 16 + bsel]));
                mma16816(acc[nb], afh[kc], bh2);
                mma16816(acc[nb], afh[kc], bl2);
                mma16816(acc[nb], afl[kc], bh2);
            }
        }
    }
}

// h = x @ w_in^T + b_in: fp32 out + hi/lo split, row-major [m][256]
__global__ __launch_bounds__(128) void gemm_h(const float* __restrict__ bias)
{
    __shared__ __half Ash[64][72], Asl[64][72], Wsh[64][72], Wsl[64][72];
    const int m0 = blockIdx.x * 64, n0 = blockIdx.y * 64;
    const int tid = threadIdx.x;
    const int wid = tid >> 5, lane = tid & 31;
    const int g = lane >> 2, t4 = lane & 3;

    float acc[8][4];
#pragma unroll
    for (int i = 0; i < 8; i++)
#pragma unroll
        for (int j = 0; j < 4; j++) acc[i][j] = 0.f;

    gemm_core(g_xh, g_xl, g_wsh[0], g_wsl[0], Ash, Asl, Wsh, Wsl, m0, n0, tid, acc);

    const int r0 = m0 + 16 * wid + g;
    const int r1 = r0 + 8;
#pragma unroll
    for (int nb = 0; nb < 8; nb++) {
        int c0 = n0 + 8 * nb + 2 * t4;
        float bx = bias[c0], by = bias[c0 + 1];
        float v00 = acc[nb][0] + bx, v01 = acc[nb][1] + by;
        float v10 = acc[nb][2] + bx, v11 = acc[nb][3] + by;
        *(float2*)&g_h[(size_t)r0 * EE + c0] = make_float2(v00, v01);
        *(float2*)&g_h[(size_t)r1 * EE + c0] = make_float2(v10, v11);
        __half h00 = __float2half_rn(v00), h01 = __float2half_rn(v01);
        __half h10 = __float2half_rn(v10), h11 = __float2half_rn(v11);
        *(uint32_t*)&g_hh[(size_t)r0 * EE + c0] = pack_half2(h00, h01);
        *(uint32_t*)&g_hh[(size_t)r1 * EE + c0] = pack_half2(h10, h11);
        *(uint32_t*)&g_hl[(size_t)r0 * EE + c0] =
            pack_half2(__float2half_rn(v00 - __half2float(h00)),
                       __float2half_rn(v01 - __half2float(h01)));
        *(uint32_t*)&g_hl[(size_t)r1 * EE + c0] =
            pack_half2(__float2half_rn(v10 - __half2float(h10)),
                       __float2half_rn(v11 - __half2float(h11)));
    }
}

// q (z=0, scale 0.125), k (z=1), u (z=2) in one launch.
__global__ __launch_bounds__(128) void gemm_qku(const float* __restrict__ bias_q,
                                                const float* __restrict__ bias_k,
                                                const float* __restrict__ bias_v)
{
    __shared__ __half Ash[64][72], Asl[64][72], Wsh[64][72], Wsl[64][72];
    const int m0 = blockIdx.x * 64, n0 = blockIdx.y * 64;
    const int z = blockIdx.z;
    const int tid = threadIdx.x;
    const int wid = tid >> 5, lane = tid & 31;
    const int g = lane >> 2, t4 = lane & 3;

    const __half* Wh = g_wsh[z + 1];
    const __half* Wl = g_wsl[z + 1];
    const float* bias = (z == 0) ? bias_q : (z == 1) ? bias_k : bias_v;

    float acc[8][4];
#pragma unroll
    for (int i = 0; i < 8; i++)
#pragma unroll
        for (int j = 0; j < 4; j++) acc[i][j] = 0.f;

    gemm_core(g_hh, g_hl, Wh, Wl, Ash, Asl, Wsh, Wsl, m0, n0, tid, acc);

    const int r0 = m0 + 16 * wid + g;
    if (z == 2) {
        // u epilogue: dot with w_eff slice, quad-reduce, scalar store
        float z0 = 0.f, z1 = 0.f;
#pragma unroll
        for (int nb = 0; nb < 8; nb++) {
            int c0 = n0 + 8 * nb + 2 * t4;
            float bx = bias[c0], by = bias[c0 + 1];
            float wx = g_weff[c0], wy = g_weff[c0 + 1];
            z0 += (acc[nb][0] + bx) * wx + (acc[nb][1] + by) * wy;
            z1 += (acc[nb][2] + bx) * wx + (acc[nb][3] + by) * wy;
        }
#pragma unroll
        for (int m = 1; m <= 2; m <<= 1) {
            z0 += __shfl_xor_sync(0xffffffffu, z0, m);
            z1 += __shfl_xor_sync(0xffffffffu, z1, m);
        }
        if (t4 == 0) {
            int hh = n0 >> 6;
            int b = r0 >> 11, t = r0 & (TT - 1);
            size_t base = (size_t)(b * HH + hh) * TT;
            g_u[base + t] = z0;
            g_u[base + t + 8] = z1;
        }
    } else {
        __half* oh = z ? g_kh : g_qh;
        __half* ol = z ? g_kl : g_ql;
        const float scale = z ? 1.0f : 0.125f;
#pragma unroll
        for (int nb = 0; nb < 8; nb++) {
            int c0 = n0 + 8 * nb + 2 * t4;
            float bx = bias[c0], by = bias[c0 + 1];
            float v00 = (acc[nb][0] + bx) * scale, v01 = (acc[nb][1] + by) * scale;
            float v10 = (acc[nb][2] + bx) * scale, v11 = (acc[nb][3] + by) * scale;
            int hh = c0 >> 6, d = c0 & 63;
            int b = r0 >> 11, t0n = r0 & (TT - 1);
            size_t base = ((size_t)((b * HH + hh) * TT)) * HD + d;
            size_t i0 = base + (size_t)t0n * HD;
            size_t i1 = base + (size_t)(t0n + 8) * HD;
            __half h00 = __float2half_rn(v00), h01 = __float2half_rn(v01);
            __half h10 = __float2half_rn(v10), h11 = __float2half_rn(v11);
            *(uint32_t*)&oh[i0] = pack_half2(h00, h01);
            *(uint32_t*)&oh[i1] = pack_half2(h10, h11);
            *(uint32_t*)&ol[i0] =
                pack_half2(__float2half_rn(v00 - __half2float(h00)),
                           __float2half_rn(v01 - __half2float(h01)));
            *(uint32_t*)&ol[i1] =
                pack_half2(__float2half_rn(v10 - __half2float(h10)),
                           __float2half_rn(v11 - __half2float(h11)));
        }
    }
}

// ---------------------------------------------------------------------------
// 64-token chunk sums of h: g_chs[b][c][d] = sum_{t in chunk} h[b][t][d]
__global__ __launch_bounds__(256) void chs_kernel()
{
    int b = blockIdx.x, c = blockIdx.y, d = threadIdx.x;
    const float* p = g_h + ((size_t)b * TT + c * 64) * EE + d;
    float s = 0.f;
#pragma unroll 8
    for (int i = 0; i < 64; i++) s += p[(size_t)i * EE];
    g_chs[b][c][d] = s;
}

// ---------------------------------------------------------------------------
// Flash attention, S-only (R8 shape): z[t] = (sum p*u)/(sum p), p = exp(q.k/8).
// fp16 3-MMA hi/lo split (fp32-accurate). CTA: 128 threads (4 warps), 64 q rows.
struct AttnSmem {
    __half kh[64][72];
    __half kl[64][72];
    float u[64];
};

__global__ __launch_bounds__(128) void attn_mma()
{
    __shared__ AttnSmem sm;
    const int tid = threadIdx.x;
    const int wid = tid >> 5;
    const int lane = tid & 31;
    const int bh = blockIdx.y;
    const int qt0 = blockIdx.x * 64;
    const int b = bh >> 2, hh = bh & 3;
    const int g = lane >> 2, t4 = lane & 3;

    // ---- stage Q (hi/lo) into kh/kl, extract A-fragments ----
    {
        const uint4* Qh = (const uint4*)(g_qh + ((size_t)bh * TT + qt0) * HD);
        const uint4* Ql = (const uint4*)(g_ql + ((size_t)bh * TT + qt0) * HD);
#pragma unroll
        for (int i = tid; i < 512; i += 128) {
            int r = i >> 3, c8 = i & 7;
            *(uint4*)&sm.kh[r][c8 * 8] = Qh[i];
            *(uint4*)&sm.kl[r][c8 * 8] = Ql[i];
        }
    }
    __syncthreads();

    uint32_t qfh[4][4], qfl[4][4];
    {
        int arow = 16 * wid + (lane & 15);
        int acolsel = (lane & 16) ? 8 : 0;
#pragma unroll
        for (int kc = 0; kc < 4; kc++) {
            ldmatrix_x4(qfh[kc], smem_u32(&sm.kh[arow][kc * 16 + acolsel]));
            ldmatrix_x4(qfl[kc], smem_u32(&sm.kl[arow][kc * 16 + acolsel]));
        }
    }
    __syncthreads();

    float lacc0 = 0.f, lacc8 = 0.f, zn0 = 0.f, zn8 = 0.f;

    const int brow4 = ((lane & 16) ? 8 : 0) + (lane & 7);
    const int bsel8 = (lane & 8) ? 8 : 0;

    for (int kt = 0; kt < TT / 64; kt++) {
        // ---- load K tile (hi/lo) + u segment ----
        {
            const size_t base = ((size_t)bh * TT + kt * 64) * HD;
            const uint4* Kh = (const uint4*)(g_kh + base);
            const uint4* Kl = (const uint4*)(g_kl + base);
#pragma unroll
            for (int i = tid; i < 512; i += 128) {
                int r = i >> 3, c8 = i & 7;
                *(uint4*)&sm.kh[r][c8 * 8] = Kh[i];
                *(uint4*)&sm.kl[r][c8 * 8] = Kl[i];
            }
            if (tid < 16)
                *(float4*)&sm.u[tid * 4] =
                    *(const float4*)&g_u[(size_t)bh * TT + kt * 64 + tid * 4];
        }
        __syncthreads();

        // ---- S = Q K^T, 3-way split, x4 B-loads over nb pairs ----
        float S[8][4];
#pragma unroll
        for (int i = 0; i < 8; i++)
#pragma unroll
            for (int j = 0; j < 4; j++) S[i][j] = 0.f;
#pragma unroll
        for (int kc = 0; kc < 4; kc++) {
#pragma unroll
            for (int nbp = 0; nbp < 4; nbp++) {
                uint32_t bf4[4], bl4[4];
                ldmatrix_x4(bf4, smem_u32(&sm.kh[16 * nbp + brow4][16 * kc + bsel8]));
                ldmatrix_x4(bl4, smem_u32(&sm.kl[16 * nbp + brow4][16 * kc + bsel8]));
                mma16816(S[2 * nbp],     qfh[kc], bf4);
                mma16816(S[2 * nbp],     qfh[kc], bl4);
                mma16816(S[2 * nbp],     qfl[kc], bf4);
                mma16816(S[2 * nbp + 1], qfh[kc], bf4 + 2);
                mma16816(S[2 * nbp + 1], qfh[kc], bl4 + 2);
                mma16816(S[2 * nbp + 1], qfl[kc], bf4 + 2);
            }
        }

        // ---- p = exp(s); accumulate l and z-numerator ----
#pragma unroll
        for (int nb = 0; nb < 8; nb++) {
            float2 uu = *(const float2*)&sm.u[8 * nb + 2 * t4];
            float p0 = __expf(S[nb][0]);
            float p1 = __expf(S[nb][1]);
            float p2 = __expf(S[nb][2]);
            float p3 = __expf(S[nb][3]);
            lacc0 += p0 + p1;
            lacc8 += p2 + p3;
            zn0 += p0 * uu.x + p1 * uu.y;
            zn8 += p2 * uu.x + p3 * uu.y;
        }
        __syncthreads();
    }

    // reduce across the 4 lanes of each row group
#pragma unroll
    for (int m = 1; m <= 2; m <<= 1) {
        lacc0 += __shfl_xor_sync(0xffffffffu, lacc0, m);
        lacc8 += __shfl_xor_sync(0xffffffffu, lacc8, m);
        zn0 += __shfl_xor_sync(0xffffffffu, zn0, m);
        zn8 += __shfl_xor_sync(0xffffffffu, zn8, m);
    }
    if (t4 == 0) {
        int row = qt0 + 16 * wid + g;
        g_zp[hh][b * TT + row] = zn0 / lacc0;
        g_zp[hh][b * TT + row + 8] = zn8 / lacc8;
    }
}

// ---------------------------------------------------------------------------
// bs[t] = sigmoid(sum_h zp[h][t] + b_eff)
__global__ __launch_bounds__(256) void zsig_kernel()
{
    int t = blockIdx.x * 256 + threadIdx.x;
    float z = g_zp[0][t] + g_zp[1][t] + g_zp[2][t] + g_zp[3][t] + g_weff[EE];
    g_bs[t] = 1.0f / (1.0f + expf(-z));
}

// ---------------------------------------------------------------------------
// Per batch: fp64 cumsum -> pid -> segment means (chunk sums + edges) -> proj
__global__ __launch_bounds__(256) void finalize_kernel(const float* __restrict__ w_pr,
                                                       const float* __restrict__ b_pr,
                                                       float* __restrict__ out)
{
    __shared__ float  sc[TT];
    __shared__ double sd[TT];
    __shared__ double part[256];
    __shared__ unsigned char pids[TT];
    __shared__ int starts[PP + 1];
    __shared__ float pe[PP][EE];

    const int b = blockIdx.x;
    const int tid = threadIdx.x;

    for (int t = tid; t < TT; t += 256) sc[t] = g_bs[b * TT + t];
    __syncthreads();

    {
        double s = 0.0;
#pragma unroll
        for (int i = 0; i < 8; i++) s += (double)sc[tid * 8 + i];
        part[tid] = s;
    }
    __syncthreads();
    if (tid == 0) {
        double run = 0.0;
        for (int i = 0; i < 256; i++) { double v = part[i]; part[i] = run; run += v; }
    }
    __syncthreads();
    {
        double c = part[tid];
#pragma unroll
        for (int i = 0; i < 8; i++) { c += (double)sc[tid * 8 + i]; sd[tid * 8 + i] = c; }
    }
    __syncthreads();

    double total = sd[TT - 1];
    double inv = 1.0 / fmax(total, 1e-6);
    for (int t = tid; t < TT; t += 256) {
        int p = (int)(sd[t] * inv * (double)PP);
        pids[t] = (unsigned char)(p > PP - 1 ? PP - 1 : p);
    }
    __syncthreads();

    if (tid == 0) {
        int cur = pids[0];
        for (int p = 0; p <= cur; p++) starts[p] = 0;
        for (int t = 1; t < TT; t++) {
            int p = pids[t];
            while (cur < p) starts[++cur] = t;
        }
        while (cur < PP) starts[++cur] = TT;
    }
    __syncthreads();

    // segment means via chunk sums + edge tokens; thread owns dim d = tid
    const float* hb = g_h + (size_t)b * TT * EE;
    for (int p = 0; p < PP; p++) {
        int s0 = starts[p], s1 = starts[p + 1];
        float sum = 0.f;
        int cs = (s0 + 63) >> 6, ce = s1 >> 6;
        if (cs <= ce) {
            for (int c = cs; c < ce; c++) sum += g_chs[b][c][tid];
            for (int t = s0; t < cs * 64; t++) sum += hb[(size_t)t * EE + tid];
            for (int t = ce * 64; t < s1; t++) sum += hb[(size_t)t * EE + tid];
        } else {
            for (int t = s0; t < s1; t++) sum += hb[(size_t)t * EE + tid];
        }
        float cnt = (float)(s1 - s0);
        pe[p][tid] = sum / fmaxf(cnt, 1.0f);
    }
    __syncthreads();

    // out[b][p][n] = pe[p].w_pr[n] + b_pr[n]; thread owns n = tid
    float bn = b_pr[tid];
    const float* wrow = w_pr + (size_t)tid * EE;
    for (int p = 0; p < PP; p++) {
        float a0 = 0.f, a1 = 0.f;
#pragma unroll 8
        for (int d = 0; d < EE; d += 2) {
            a0 += pe[p][d]     * wrow[d];
            a1 += pe[p][d + 1] * wrow[d + 1];
        }
        out[(size_t)(b * PP + p) * EE + tid] = bn + a0 + a1;
    }
}

// ---------------------------------------------------------------------------
extern "C" void kernel_launch(void* const* d_in, const int* in_sizes, int n_in,
                              void* d_out, int out_size)
{
    SplitArgs sa;
    sa.x    = (const float*)d_in[0];
    sa.w_in = (const float*)d_in[1];
    const float* b_in = (const float*)d_in[2];
    sa.w_q  = (const float*)d_in[3];
    const float* b_q  = (const float*)d_in[4];
    sa.w_k  = (const float*)d_in[5];
    const float* b_k  = (const float*)d_in[6];
    sa.w_v  = (const float*)d_in[7];
    const float* b_v  = (const float*)d_in[8];
    sa.w_o  = (const float*)d_in[9];
    sa.b_o  = (const float*)d_in[10];
    sa.w_bd = (const float*)d_in[11];
    sa.b_bd = (const float*)d_in[12];
    const float* w_pr = (const float*)d_in[13];
    const float* b_pr = (const float*)d_in[14];
    float* out = (float*)d_out;

    // launch 1: all splits + weff
    split_all<<<4353, 256>>>(sa);

    // launch 2: h
    gemm_h<<<dim3(BT / 64, EE / 64), 128>>>(b_in);
    // launch 3: q + k + u fused via grid.z
    gemm_qku<<<dim3(BT / 64, EE / 64, 3), 128>>>(b_q, b_k, b_v);

    // launch 4: attention (ncu capture slot = harness+2 -> our #4)
    attn_mma<<<dim3(TT / 64, NBH), 128>>>();

    chs_kernel<<<dim3(BB, 32), 256>>>();
    zsig_kernel<<<BT / 256, 256>>>();
    finalize_kernel<<<BB, 256>>>(w_pr, b_pr, out);
}

// round 12
// speedup vs baseline: 1.1878x; 1.1089x over previous
#include <cuda_runtime.h>
#include <cuda_fp16.h>
#include <math.h>
#include <stdint.h>

// Problem constants
#define BB   8
#define TT   2048
#define EE   256
#define HH   4
#define HD   64
#define PP   8
#define BT   (BB*TT)          // 16384
#define NBH  (BB*HH)          // 32

// ---------------- scratch (device globals; no allocation allowed) -----------
__device__ float g_h[BT*EE];
__device__ float g_bs[BT];
__device__ float g_weff[EE+1];       // w_eff[256] + b_eff
__device__ float g_zp[HH][BT];       // per-head boundary partials
__device__ float g_chs[BB][32][EE];  // 64-token chunk sums of h
__device__ float g_u[NBH*TT];        // u[bh][t] = v[bh][t] . w_eff_slice(h)
// fp16 hi/lo splits
__device__ __half g_xh[BT*EE], g_xl[BT*EE];
__device__ __half g_hh[BT*EE], g_hl[BT*EE];
__device__ __half g_wsh[4][EE*EE], g_wsl[4][EE*EE];   // w_in, w_q, w_k, w_v
// [bh][t][64] layouts
__device__ __half g_qh[NBH*TT*HD], g_ql[NBH*TT*HD];
__device__ __half g_kh[NBH*TT*HD], g_kl[NBH*TT*HD];

// ============================ warp-mma helpers ==============================
__device__ __forceinline__ uint32_t smem_u32(const void* p) {
    uint32_t a;
    asm("{ .reg .u64 tmp; cvta.to.shared.u64 tmp, %1; cvt.u32.u64 %0, tmp; }"
        : "=r"(a) : "l"(p));
    return a;
}
__device__ __forceinline__ void ldmatrix_x4(uint32_t* r, uint32_t addr) {
    asm volatile("ldmatrix.sync.aligned.m8n8.x4.shared.b16 {%0,%1,%2,%3}, [%4];"
                 : "=r"(r[0]), "=r"(r[1]), "=r"(r[2]), "=r"(r[3]) : "r"(addr));
}
__device__ __forceinline__ void ldmatrix_x2(uint32_t* r, uint32_t addr) {
    asm volatile("ldmatrix.sync.aligned.m8n8.x2.shared.b16 {%0,%1}, [%2];"
                 : "=r"(r[0]), "=r"(r[1]) : "r"(addr));
}
__device__ __forceinline__ void mma16816(float* d, const uint32_t* a, const uint32_t* b) {
    asm volatile(
        "mma.sync.aligned.m16n8k16.row.col.f32.f16.f16.f32 "
        "{%0,%1,%2,%3}, {%4,%5,%6,%7}, {%8,%9}, {%0,%1,%2,%3};"
        : "+f"(d[0]), "+f"(d[1]), "+f"(d[2]), "+f"(d[3])
        : "r"(a[0]), "r"(a[1]), "r"(a[2]), "r"(a[3]), "r"(b[0]), "r"(b[1]));
}
__device__ __forceinline__ uint32_t pack_half2(__half lo, __half hi) {
    return (uint32_t)__half_as_ushort(lo) | ((uint32_t)__half_as_ushort(hi) << 16);
}
#define CP_ASYNC16(smem, gptr) \
    asm volatile("cp.async.cg.shared.global [%0], [%1], 16;" :: "r"(smem), "l"(gptr))
#define CP_COMMIT() asm volatile("cp.async.commit_group;" ::: "memory")
#define CP_WAIT0()  asm volatile("cp.async.wait_group 0;" ::: "memory")

// ---------------------------------------------------------------------------
// Fused: x/w_in/w_q/w_k/w_v fp16 hi/lo splits + weff computation.
struct SplitArgs {
    const float *x, *w_in, *w_q, *w_k, *w_v, *w_o, *w_bd, *b_o, *b_bd;
};

__device__ __forceinline__ void do_split4(const float* __restrict__ src,
                                          __half* __restrict__ dh,
                                          __half* __restrict__ dl, int i)
{
    float4 v = ((const float4*)src)[i];
    __half h0 = __float2half_rn(v.x), h1 = __float2half_rn(v.y);
    __half h2 = __float2half_rn(v.z), h3 = __float2half_rn(v.w);
    __half l0 = __float2half_rn(v.x - __half2float(h0));
    __half l1 = __float2half_rn(v.y - __half2float(h1));
    __half l2 = __float2half_rn(v.z - __half2float(h2));
    __half l3 = __float2half_rn(v.w - __half2float(h3));
    ((uint2*)dh)[i] = make_uint2(pack_half2(h0, h1), pack_half2(h2, h3));
    ((uint2*)dl)[i] = make_uint2(pack_half2(l0, l1), pack_half2(l2, l3));
}

__global__ __launch_bounds__(256) void split_all(SplitArgs a)
{
    int blk = blockIdx.x;
    int tid = threadIdx.x;
    if (blk < 4096) {
        do_split4(a.x, g_xh, g_xl, blk * 256 + tid);
    } else if (blk < 4352) {
        int w = (blk - 4096) >> 6;            // 0..3
        int i = ((blk - 4096) & 63) * 256 + tid;
        const float* src = (w == 0) ? a.w_in : (w == 1) ? a.w_q : (w == 2) ? a.w_k : a.w_v;
        do_split4(src, g_wsh[w], g_wsl[w], i);
    } else {
        int j = tid;
        float s = 0.f;
        for (int i = 0; i < EE; i++) s += a.w_bd[i] * a.w_o[i * EE + j];
        g_weff[j] = s;
        if (j == 0) {
            float bb = a.b_bd[0];
            for (int i = 0; i < EE; i++) bb += a.w_bd[i] * a.b_o[i];
            g_weff[EE] = bb;
        }
    }
}

// ---------------------------------------------------------------------------
// Shared GEMM mainloop: acc[8][4] += A[64,k] W^T tile, fp16 3-MMA split.
__device__ __forceinline__ void gemm_core(const __half* __restrict__ Ah,
                                          const __half* __restrict__ Al,
                                          const __half* __restrict__ Wh,
                                          const __half* __restrict__ Wl,
                                          __half (*Ash)[72], __half (*Asl)[72],
                                          __half (*Wsh)[72], __half (*Wsl)[72],
                                          int m0, int n0, int tid,
                                          float acc[8][4])
{
    const int wid = tid >> 5;
    const int lane = tid & 31;
    const int arow = 16 * wid + (lane & 15);
    const int asel = (lane & 16) ? 8 : 0;
    const int brow = lane & 7;
    const int bsel = (lane & 8) ? 8 : 0;

    for (int kc0 = 0; kc0 < EE; kc0 += 64) {
        if (kc0) __syncthreads();
#pragma unroll
        for (int j = 0; j < 4; j++) {
            int i = tid + j * 128;            // 0..511
            int r = i >> 3, c = (i & 7) * 8;
            *(uint4*)&Ash[r][c] = *(const uint4*)&Ah[(size_t)(m0 + r) * EE + kc0 + c];
            *(uint4*)&Asl[r][c] = *(const uint4*)&Al[(size_t)(m0 + r) * EE + kc0 + c];
            *(uint4*)&Wsh[r][c] = *(const uint4*)&Wh[(size_t)(n0 + r) * EE + kc0 + c];
            *(uint4*)&Wsl[r][c] = *(const uint4*)&Wl[(size_t)(n0 + r) * EE + kc0 + c];
        }
        __syncthreads();

        uint32_t afh[4][4], afl[4][4];
#pragma unroll
        for (int kc = 0; kc < 4; kc++) {
            ldmatrix_x4(afh[kc], smem_u32(&Ash[arow][kc * 16 + asel]));
            ldmatrix_x4(afl[kc], smem_u32(&Asl[arow][kc * 16 + asel]));
        }
#pragma unroll
        for (int kc = 0; kc < 4; kc++) {
#pragma unroll
            for (int nb = 0; nb < 8; nb++) {
                uint32_t bh2[2], bl2[2];
                ldmatrix_x2(bh2, smem_u32(&Wsh[8 * nb + brow][kc * 16 + bsel]));
                ldmatrix_x2(bl2, smem_u32(&Wsl[8 * nb + brow][kc * 16 + bsel]));
                mma16816(acc[nb], afh[kc], bh2);
                mma16816(acc[nb], afh[kc], bl2);
                mma16816(acc[nb], afl[kc], bh2);
            }
        }
    }
}

// h = x @ w_in^T + b_in: fp32 out + hi/lo split, row-major [m][256]
__global__ __launch_bounds__(128) void gemm_h(const float* __restrict__ bias)
{
    __shared__ __half Ash[64][72], Asl[64][72], Wsh[64][72], Wsl[64][72];
    const int m0 = blockIdx.x * 64, n0 = blockIdx.y * 64;
    const int tid = threadIdx.x;
    const int wid = tid >> 5, lane = tid & 31;
    const int g = lane >> 2, t4 = lane & 3;

    float acc[8][4];
#pragma unroll
    for (int i = 0; i < 8; i++)
#pragma unroll
        for (int j = 0; j < 4; j++) acc[i][j] = 0.f;

    gemm_core(g_xh, g_xl, g_wsh[0], g_wsl[0], Ash, Asl, Wsh, Wsl, m0, n0, tid, acc);

    const int r0 = m0 + 16 * wid + g;
    const int r1 = r0 + 8;
#pragma unroll
    for (int nb = 0; nb < 8; nb++) {
        int c0 = n0 + 8 * nb + 2 * t4;
        float bx = bias[c0], by = bias[c0 + 1];
        float v00 = acc[nb][0] + bx, v01 = acc[nb][1] + by;
        float v10 = acc[nb][2] + bx, v11 = acc[nb][3] + by;
        *(float2*)&g_h[(size_t)r0 * EE + c0] = make_float2(v00, v01);
        *(float2*)&g_h[(size_t)r1 * EE + c0] = make_float2(v10, v11);
        __half h00 = __float2half_rn(v00), h01 = __float2half_rn(v01);
        __half h10 = __float2half_rn(v10), h11 = __float2half_rn(v11);
        *(uint32_t*)&g_hh[(size_t)r0 * EE + c0] = pack_half2(h00, h01);
        *(uint32_t*)&g_hh[(size_t)r1 * EE + c0] = pack_half2(h10, h11);
        *(uint32_t*)&g_hl[(size_t)r0 * EE + c0] =
            pack_half2(__float2half_rn(v00 - __half2float(h00)),
                       __float2half_rn(v01 - __half2float(h01)));
        *(uint32_t*)&g_hl[(size_t)r1 * EE + c0] =
            pack_half2(__float2half_rn(v10 - __half2float(h10)),
                       __float2half_rn(v11 - __half2float(h11)));
    }
}

// q (z=0, scale 0.125), k (z=1), u (z=2) in one launch.
__global__ __launch_bounds__(128) void gemm_qku(const float* __restrict__ bias_q,
                                                const float* __restrict__ bias_k,
                                                const float* __restrict__ bias_v)
{
    __shared__ __half Ash[64][72], Asl[64][72], Wsh[64][72], Wsl[64][72];
    const int m0 = blockIdx.x * 64, n0 = blockIdx.y * 64;
    const int z = blockIdx.z;
    const int tid = threadIdx.x;
    const int wid = tid >> 5, lane = tid & 31;
    const int g = lane >> 2, t4 = lane & 3;

    const __half* Wh = g_wsh[z + 1];
    const __half* Wl = g_wsl[z + 1];
    const float* bias = (z == 0) ? bias_q : (z == 1) ? bias_k : bias_v;

    float acc[8][4];
#pragma unroll
    for (int i = 0; i < 8; i++)
#pragma unroll
        for (int j = 0; j < 4; j++) acc[i][j] = 0.f;

    gemm_core(g_hh, g_hl, Wh, Wl, Ash, Asl, Wsh, Wsl, m0, n0, tid, acc);

    const int r0 = m0 + 16 * wid + g;
    if (z == 2) {
        float z0 = 0.f, z1 = 0.f;
#pragma unroll
        for (int nb = 0; nb < 8; nb++) {
            int c0 = n0 + 8 * nb + 2 * t4;
            float bx = bias[c0], by = bias[c0 + 1];
            float wx = g_weff[c0], wy = g_weff[c0 + 1];
            z0 += (acc[nb][0] + bx) * wx + (acc[nb][1] + by) * wy;
            z1 += (acc[nb][2] + bx) * wx + (acc[nb][3] + by) * wy;
        }
#pragma unroll
        for (int m = 1; m <= 2; m <<= 1) {
            z0 += __shfl_xor_sync(0xffffffffu, z0, m);
            z1 += __shfl_xor_sync(0xffffffffu, z1, m);
        }
        if (t4 == 0) {
            int hh = n0 >> 6;
            int b = r0 >> 11, t = r0 & (TT - 1);
            size_t base = (size_t)(b * HH + hh) * TT;
            g_u[base + t] = z0;
            g_u[base + t + 8] = z1;
        }
    } else {
        __half* oh = z ? g_kh : g_qh;
        __half* ol = z ? g_kl : g_ql;
        const float scale = z ? 1.0f : 0.125f;
#pragma unroll
        for (int nb = 0; nb < 8; nb++) {
            int c0 = n0 + 8 * nb + 2 * t4;
            float bx = bias[c0], by = bias[c0 + 1];
            float v00 = (acc[nb][0] + bx) * scale, v01 = (acc[nb][1] + by) * scale;
            float v10 = (acc[nb][2] + bx) * scale, v11 = (acc[nb][3] + by) * scale;
            int hh = c0 >> 6, d = c0 & 63;
            int b = r0 >> 11, t0n = r0 & (TT - 1);
            size_t base = ((size_t)((b * HH + hh) * TT)) * HD + d;
            size_t i0 = base + (size_t)t0n * HD;
            size_t i1 = base + (size_t)(t0n + 8) * HD;
            __half h00 = __float2half_rn(v00), h01 = __float2half_rn(v01);
            __half h10 = __float2half_rn(v10), h11 = __float2half_rn(v11);
            *(uint32_t*)&oh[i0] = pack_half2(h00, h01);
            *(uint32_t*)&oh[i1] = pack_half2(h10, h11);
            *(uint32_t*)&ol[i0] =
                pack_half2(__float2half_rn(v00 - __half2float(h00)),
                           __float2half_rn(v01 - __half2float(h01)));
            *(uint32_t*)&ol[i1] =
                pack_half2(__float2half_rn(v10 - __half2float(h10)),
                           __float2half_rn(v11 - __half2float(h11)));
        }
    }
}

// ---------------------------------------------------------------------------
// 64-token chunk sums of h: g_chs[b][c][d] = sum_{t in chunk} h[b][t][d]
__global__ __launch_bounds__(256) void chs_kernel()
{
    int b = blockIdx.x, c = blockIdx.y, d = threadIdx.x;
    const float* p = g_h + ((size_t)b * TT + c * 64) * EE + d;
    float s = 0.f;
#pragma unroll 8
    for (int i = 0; i < 64; i++) s += p[(size_t)i * EE];
    g_chs[b][c][d] = s;
}

// ---------------------------------------------------------------------------
// Flash attention v4, S-only, cp.async double-buffered K, ONE sync per tile.
// z[t] = (sum p*u)/(sum p), p = exp(q.k/8); fp16 3-MMA hi/lo split.
// CTA: 128 threads (4 warps), 64 q rows. smem ~37.4 KB (occ stays reg-limited).
struct AttnSmem {
    __half kh[2][64][72];
    __half kl[2][64][72];
    float u[2][64];
};

__global__ __launch_bounds__(128) void attn_mma()
{
    __shared__ AttnSmem sm;
    const int tid = threadIdx.x;
    const int wid = tid >> 5;
    const int lane = tid & 31;
    const int bh = blockIdx.y;
    const int qt0 = blockIdx.x * 64;
    const int b = bh >> 2, hh = bh & 3;
    const int g = lane >> 2, t4 = lane & 3;

    // ---- stage Q (hi/lo) through stage 0, extract A-fragments ----
    {
        const uint4* Qh = (const uint4*)(g_qh + ((size_t)bh * TT + qt0) * HD);
        const uint4* Ql = (const uint4*)(g_ql + ((size_t)bh * TT + qt0) * HD);
#pragma unroll
        for (int i = tid; i < 512; i += 128) {
            int r = i >> 3, c8 = i & 7;
            *(uint4*)&sm.kh[0][r][c8 * 8] = Qh[i];
            *(uint4*)&sm.kl[0][r][c8 * 8] = Ql[i];
        }
    }
    __syncthreads();

    uint32_t qfh[4][4], qfl[4][4];
    {
        int arow = 16 * wid + (lane & 15);
        int acolsel = (lane & 16) ? 8 : 0;
#pragma unroll
        for (int kc = 0; kc < 4; kc++) {
            ldmatrix_x4(qfh[kc], smem_u32(&sm.kh[0][arow][kc * 16 + acolsel]));
            ldmatrix_x4(qfl[kc], smem_u32(&sm.kl[0][arow][kc * 16 + acolsel]));
        }
    }
    __syncthreads();

    // ---- prefetch tile 0 into stage 0 (cp.async) ----
    {
        const __half* Kh = g_kh + (size_t)bh * TT * HD;
        const __half* Kl = g_kl + (size_t)bh * TT * HD;
#pragma unroll
        for (int i = tid; i < 512; i += 128) {
            int r = i >> 3, c8 = i & 7;
            CP_ASYNC16(smem_u32(&sm.kh[0][r][c8 * 8]), Kh + r * 64 + c8 * 8);
            CP_ASYNC16(smem_u32(&sm.kl[0][r][c8 * 8]), Kl + r * 64 + c8 * 8);
        }
        if (tid < 16)
            CP_ASYNC16(smem_u32(&sm.u[0][tid * 4]), g_u + (size_t)bh * TT + tid * 4);
        CP_COMMIT();
    }

    float lacc0 = 0.f, lacc8 = 0.f, zn0 = 0.f, zn8 = 0.f;

    const int brow4 = ((lane & 16) ? 8 : 0) + (lane & 7);
    const int bsel8 = (lane & 8) ? 8 : 0;

    for (int kt = 0; kt < TT / 64; kt++) {
        const int cur = kt & 1;
        CP_WAIT0();          // tile kt landed (this thread's chunks)
        __syncthreads();     // all threads' chunks visible; prev compute done

        // prefetch tile kt+1 into the stage just freed by iteration kt-1
        if (kt + 1 < TT / 64) {
            const size_t base = ((size_t)bh * TT + (kt + 1) * 64) * HD;
            const __half* Kh = g_kh + base;
            const __half* Kl = g_kl + base;
            const int ns = cur ^ 1;
#pragma unroll
            for (int i = tid; i < 512; i += 128) {
                int r = i >> 3, c8 = i & 7;
                CP_ASYNC16(smem_u32(&sm.kh[ns][r][c8 * 8]), Kh + r * 64 + c8 * 8);
                CP_ASYNC16(smem_u32(&sm.kl[ns][r][c8 * 8]), Kl + r * 64 + c8 * 8);
            }
            if (tid < 16)
                CP_ASYNC16(smem_u32(&sm.u[ns][tid * 4]),
                           g_u + (size_t)bh * TT + (kt + 1) * 64 + tid * 4);
            CP_COMMIT();
        }

        // ---- S = Q K^T, 3-way split, x4 B-loads over nb pairs ----
        float S[8][4];
#pragma unroll
        for (int i = 0; i < 8; i++)
#pragma unroll
            for (int j = 0; j < 4; j++) S[i][j] = 0.f;
#pragma unroll
        for (int kc = 0; kc < 4; kc++) {
#pragma unroll
            for (int nbp = 0; nbp < 4; nbp++) {
                uint32_t bf4[4], bl4[4];
                ldmatrix_x4(bf4, smem_u32(&sm.kh[cur][16 * nbp + brow4][16 * kc + bsel8]));
                ldmatrix_x4(bl4, smem_u32(&sm.kl[cur][16 * nbp + brow4][16 * kc + bsel8]));
                mma16816(S[2 * nbp],     qfh[kc], bf4);
                mma16816(S[2 * nbp],     qfh[kc], bl4);
                mma16816(S[2 * nbp],     qfl[kc], bf4);
                mma16816(S[2 * nbp + 1], qfh[kc], bf4 + 2);
                mma16816(S[2 * nbp + 1], qfh[kc], bl4 + 2);
                mma16816(S[2 * nbp + 1], qfl[kc], bf4 + 2);
            }
        }

        // ---- p = exp(s); accumulate l and z-numerator ----
#pragma unroll
        for (int nb = 0; nb < 8; nb++) {
            float2 uu = *(const float2*)&sm.u[cur][8 * nb + 2 * t4];
            float p0 = __expf(S[nb][0]);
            float p1 = __expf(S[nb][1]);
            float p2 = __expf(S[nb][2]);
            float p3 = __expf(S[nb][3]);
            lacc0 += p0 + p1;
            lacc8 += p2 + p3;
            zn0 += p0 * uu.x + p1 * uu.y;
            zn8 += p2 * uu.x + p3 * uu.y;
        }
    }

    // reduce across the 4 lanes of each row group
#pragma unroll
    for (int m = 1; m <= 2; m <<= 1) {
        lacc0 += __shfl_xor_sync(0xffffffffu, lacc0, m);
        lacc8 += __shfl_xor_sync(0xffffffffu, lacc8, m);
        zn0 += __shfl_xor_sync(0xffffffffu, zn0, m);
        zn8 += __shfl_xor_sync(0xffffffffu, zn8, m);
    }
    if (t4 == 0) {
        int row = qt0 + 16 * wid + g;
        g_zp[hh][b * TT + row] = zn0 / lacc0;
        g_zp[hh][b * TT + row + 8] = zn8 / lacc8;
    }
}

// ---------------------------------------------------------------------------
// bs[t] = sigmoid(sum_h zp[h][t] + b_eff)
__global__ __launch_bounds__(256) void zsig_kernel()
{
    int t = blockIdx.x * 256 + threadIdx.x;
    float z = g_zp[0][t] + g_zp[1][t] + g_zp[2][t] + g_zp[3][t] + g_weff[EE];
    g_bs[t] = 1.0f / (1.0f + expf(-z));
}

// ---------------------------------------------------------------------------
// Per batch: fp64 cumsum -> pid -> segment means (chunk sums + edges) -> proj
__global__ __launch_bounds__(256) void finalize_kernel(const float* __restrict__ w_pr,
                                                       const float* __restrict__ b_pr,
                                                       float* __restrict__ out)
{
    __shared__ float  sc[TT];
    __shared__ double sd[TT];
    __shared__ double part[256];
    __shared__ unsigned char pids[TT];
    __shared__ int starts[PP + 1];
    __shared__ float pe[PP][EE];

    const int b = blockIdx.x;
    const int tid = threadIdx.x;

    for (int t = tid; t < TT; t += 256) sc[t] = g_bs[b * TT + t];
    __syncthreads();

    {
        double s = 0.0;
#pragma unroll
        for (int i = 0; i < 8; i++) s += (double)sc[tid * 8 + i];
        part[tid] = s;
    }
    __syncthreads();
    if (tid == 0) {
        double run = 0.0;
        for (int i = 0; i < 256; i++) { double v = part[i]; part[i] = run; run += v; }
    }
    __syncthreads();
    {
        double c = part[tid];
#pragma unroll
        for (int i = 0; i < 8; i++) { c += (double)sc[tid * 8 + i]; sd[tid * 8 + i] = c; }
    }
    __syncthreads();

    double total = sd[TT - 1];
    double inv = 1.0 / fmax(total, 1e-6);
    for (int t = tid; t < TT; t += 256) {
        int p = (int)(sd[t] * inv * (double)PP);
        pids[t] = (unsigned char)(p > PP - 1 ? PP - 1 : p);
    }
    __syncthreads();

    // parallel boundary-start detection (pids monotone non-decreasing)
    if (tid == 0) {
        int p0 = pids[0];
        for (int p = 0; p <= p0; p++) starts[p] = 0;
        int plast = pids[TT - 1];
        for (int p = plast + 1; p <= PP; p++) starts[p] = TT;
    }
    for (int t = tid + 1; t < TT; t += 256) {
        int pprev = pids[t - 1], pcur = pids[t];
        for (int p = pprev + 1; p <= pcur; p++) starts[p] = t;
    }
    __syncthreads();

    // segment means via chunk sums + edge tokens; thread owns dim d = tid
    const float* hb = g_h + (size_t)b * TT * EE;
    for (int p = 0; p < PP; p++) {
        int s0 = starts[p], s1 = starts[p + 1];
        float sum = 0.f;
        int cs = (s0 + 63) >> 6, ce = s1 >> 6;
        if (cs <= ce) {
            for (int c = cs; c < ce; c++) sum += g_chs[b][c][tid];
            for (int t = s0; t < cs * 64; t++) sum += hb[(size_t)t * EE + tid];
            for (int t = ce * 64; t < s1; t++) sum += hb[(size_t)t * EE + tid];
        } else {
            for (int t = s0; t < s1; t++) sum += hb[(size_t)t * EE + tid];
        }
        float cnt = (float)(s1 - s0);
        pe[p][tid] = sum / fmaxf(cnt, 1.0f);
    }
    __syncthreads();

    // out[b][p][n] = pe[p].w_pr[n] + b_pr[n]; thread owns n = tid
    float bn = b_pr[tid];
    const float* wrow = w_pr + (size_t)tid * EE;
    for (int p = 0; p < PP; p++) {
        float a0 = 0.f, a1 = 0.f;
#pragma unroll 8
        for (int d = 0; d < EE; d += 2) {
            a0 += pe[p][d]     * wrow[d];
            a1 += pe[p][d + 1] * wrow[d + 1];
        }
        out[(size_t)(b * PP + p) * EE + tid] = bn + a0 + a1;
    }
}

// ---------------------------------------------------------------------------
extern "C" void kernel_launch(void* const* d_in, const int* in_sizes, int n_in,
                              void* d_out, int out_size)
{
    SplitArgs sa;
    sa.x    = (const float*)d_in[0];
    sa.w_in = (const float*)d_in[1];
    const float* b_in = (const float*)d_in[2];
    sa.w_q  = (const float*)d_in[3];
    const float* b_q  = (const float*)d_in[4];
    sa.w_k  = (const float*)d_in[5];
    const float* b_k  = (const float*)d_in[6];
    sa.w_v  = (const float*)d_in[7];
    const float* b_v  = (const float*)d_in[8];
    sa.w_o  = (const float*)d_in[9];
    sa.b_o  = (const float*)d_in[10];
    sa.w_bd = (const float*)d_in[11];
    sa.b_bd = (const float*)d_in[12];
    const float* w_pr = (const float*)d_in[13];
    const float* b_pr = (const float*)d_in[14];
    float* out = (float*)d_out;

    // launch 1: all splits + weff
    split_all<<<4353, 256>>>(sa);

    // launch 2: h
    gemm_h<<<dim3(BT / 64, EE / 64), 128>>>(b_in);
    // launch 3: q + k + u fused via grid.z
    gemm_qku<<<dim3(BT / 64, EE / 64, 3), 128>>>(b_q, b_k, b_v);

    // launch 4: attention (ncu capture slot)
    attn_mma<<<dim3(TT / 64, NBH), 128>>>();

    chs_kernel<<<dim3(BB, 32), 256>>>();
    zsig_kernel<<<BT / 256, 256>>>();
    finalize_kernel<<<BB, 256>>>(w_pr, b_pr, out);
}

// round 13
// speedup vs baseline: 1.2160x; 1.0238x over previous
#include <cuda_runtime.h>
#include <cuda_fp16.h>
#include <math.h>
#include <stdint.h>

// Problem constants
#define BB   8
#define TT   2048
#define EE   256
#define HH   4
#define HD   64
#define PP   8
#define BT   (BB*TT)          // 16384
#define NBH  (BB*HH)          // 32

// q pre-scale: (1/sqrt(64)) * log2(e)  -> softmax via bare exp2
#define QSCALE 0.18033688011112042f

// ---------------- scratch (device globals; no allocation allowed) -----------
__device__ float g_h[BT*EE];
__device__ float g_bs[BT];
__device__ float g_weff[EE+1];       // w_eff[256] + b_eff
__device__ float g_zp[HH][BT];       // per-head boundary partials
__device__ float g_chs[BB][32][EE];  // 64-token chunk sums of h
__device__ float g_u[NBH*TT];        // u[bh][t] = v[bh][t] . w_eff_slice(h)
// fp16 hi/lo splits
__device__ __half g_xh[BT*EE], g_xl[BT*EE];
__device__ __half g_hh[BT*EE], g_hl[BT*EE];
__device__ __half g_wsh[4][EE*EE], g_wsl[4][EE*EE];   // w_in, w_q, w_k, w_v
// [bh][t][64] layouts
__device__ __half g_qh[NBH*TT*HD], g_ql[NBH*TT*HD];
__device__ __half g_kh[NBH*TT*HD], g_kl[NBH*TT*HD];

// ============================ warp-mma helpers ==============================
__device__ __forceinline__ uint32_t smem_u32(const void* p) {
    uint32_t a;
    asm("{ .reg .u64 tmp; cvta.to.shared.u64 tmp, %1; cvt.u32.u64 %0, tmp; }"
        : "=r"(a) : "l"(p));
    return a;
}
__device__ __forceinline__ void ldmatrix_x4(uint32_t* r, uint32_t addr) {
    asm volatile("ldmatrix.sync.aligned.m8n8.x4.shared.b16 {%0,%1,%2,%3}, [%4];"
                 : "=r"(r[0]), "=r"(r[1]), "=r"(r[2]), "=r"(r[3]) : "r"(addr));
}
__device__ __forceinline__ void mma16816(float* d, const uint32_t* a, const uint32_t* b) {
    asm volatile(
        "mma.sync.aligned.m16n8k16.row.col.f32.f16.f16.f32 "
        "{%0,%1,%2,%3}, {%4,%5,%6,%7}, {%8,%9}, {%0,%1,%2,%3};"
        : "+f"(d[0]), "+f"(d[1]), "+f"(d[2]), "+f"(d[3])
        : "r"(a[0]), "r"(a[1]), "r"(a[2]), "r"(a[3]), "r"(b[0]), "r"(b[1]));
}
__device__ __forceinline__ uint32_t pack_half2(__half lo, __half hi) {
    return (uint32_t)__half_as_ushort(lo) | ((uint32_t)__half_as_ushort(hi) << 16);
}
__device__ __forceinline__ float fexp2(float x) {
    float r;
    asm("ex2.approx.f32 %0, %1;" : "=f"(r) : "f"(x));
    return r;
}

// ---------------------------------------------------------------------------
// Fused: x/w_in/w_q/w_k/w_v fp16 hi/lo splits + weff computation.
struct SplitArgs {
    const float *x, *w_in, *w_q, *w_k, *w_v, *w_o, *w_bd, *b_o, *b_bd;
};

__device__ __forceinline__ void do_split4(const float* __restrict__ src,
                                          __half* __restrict__ dh,
                                          __half* __restrict__ dl, int i)
{
    float4 v = ((const float4*)src)[i];
    __half h0 = __float2half_rn(v.x), h1 = __float2half_rn(v.y);
    __half h2 = __float2half_rn(v.z), h3 = __float2half_rn(v.w);
    __half l0 = __float2half_rn(v.x - __half2float(h0));
    __half l1 = __float2half_rn(v.y - __half2float(h1));
    __half l2 = __float2half_rn(v.z - __half2float(h2));
    __half l3 = __float2half_rn(v.w - __half2float(h3));
    ((uint2*)dh)[i] = make_uint2(pack_half2(h0, h1), pack_half2(h2, h3));
    ((uint2*)dl)[i] = make_uint2(pack_half2(l0, l1), pack_half2(l2, l3));
}

__global__ __launch_bounds__(256) void split_all(SplitArgs a)
{
    int blk = blockIdx.x;
    int tid = threadIdx.x;
    if (blk < 4096) {
        do_split4(a.x, g_xh, g_xl, blk * 256 + tid);
    } else if (blk < 4352) {
        int w = (blk - 4096) >> 6;            // 0..3
        int i = ((blk - 4096) & 63) * 256 + tid;
        const float* src = (w == 0) ? a.w_in : (w == 1) ? a.w_q : (w == 2) ? a.w_k : a.w_v;
        do_split4(src, g_wsh[w], g_wsl[w], i);
    } else {
        int j = tid;
        float s = 0.f;
        for (int i = 0; i < EE; i++) s += a.w_bd[i] * a.w_o[i * EE + j];
        g_weff[j] = s;
        if (j == 0) {
            float bb = a.b_bd[0];
            for (int i = 0; i < EE; i++) bb += a.w_bd[i] * a.b_o[i];
            g_weff[EE] = bb;
        }
    }
}

// ---------------------------------------------------------------------------
// Shared GEMM mainloop: acc[8][4] += A[64,k] W^T tile, fp16 3-MMA split.
// CTA: 128 threads (4 warps), tile 64(m) x 64(n). x4 B-operand ldmatrix.
__device__ __forceinline__ void gemm_core(const __half* __restrict__ Ah,
                                          const __half* __restrict__ Al,
                                          const __half* __restrict__ Wh,
                                          const __half* __restrict__ Wl,
                                          __half (*Ash)[72], __half (*Asl)[72],
                                          __half (*Wsh)[72], __half (*Wsl)[72],
                                          int m0, int n0, int tid,
                                          float acc[8][4])
{
    const int wid = tid >> 5;
    const int lane = tid & 31;
    const int arow = 16 * wid + (lane & 15);
    const int asel = (lane & 16) ? 8 : 0;
    const int brow4 = ((lane & 16) ? 8 : 0) + (lane & 7);
    const int bsel8 = (lane & 8) ? 8 : 0;

    for (int kc0 = 0; kc0 < EE; kc0 += 64) {
        if (kc0) __syncthreads();
#pragma unroll
        for (int j = 0; j < 4; j++) {
            int i = tid + j * 128;            // 0..511
            int r = i >> 3, c = (i & 7) * 8;
            *(uint4*)&Ash[r][c] = *(const uint4*)&Ah[(size_t)(m0 + r) * EE + kc0 + c];
            *(uint4*)&Asl[r][c] = *(const uint4*)&Al[(size_t)(m0 + r) * EE + kc0 + c];
            *(uint4*)&Wsh[r][c] = *(const uint4*)&Wh[(size_t)(n0 + r) * EE + kc0 + c];
            *(uint4*)&Wsl[r][c] = *(const uint4*)&Wl[(size_t)(n0 + r) * EE + kc0 + c];
        }
        __syncthreads();

        uint32_t afh[4][4], afl[4][4];
#pragma unroll
        for (int kc = 0; kc < 4; kc++) {
            ldmatrix_x4(afh[kc], smem_u32(&Ash[arow][kc * 16 + asel]));
            ldmatrix_x4(afl[kc], smem_u32(&Asl[arow][kc * 16 + asel]));
        }
#pragma unroll
        for (int kc = 0; kc < 4; kc++) {
#pragma unroll
            for (int nbp = 0; nbp < 4; nbp++) {
                uint32_t bf4[4], bl4[4];
                ldmatrix_x4(bf4, smem_u32(&Wsh[16 * nbp + brow4][16 * kc + bsel8]));
                ldmatrix_x4(bl4, smem_u32(&Wsl[16 * nbp + brow4][16 * kc + bsel8]));
                mma16816(acc[2 * nbp],     afh[kc], bf4);
                mma16816(acc[2 * nbp],     afh[kc], bl4);
                mma16816(acc[2 * nbp],     afl[kc], bf4);
                mma16816(acc[2 * nbp + 1], afh[kc], bf4 + 2);
                mma16816(acc[2 * nbp + 1], afh[kc], bl4 + 2);
                mma16816(acc[2 * nbp + 1], afl[kc], bf4 + 2);
            }
        }
    }
}

// h = x @ w_in^T + b_in: fp32 out + hi/lo split, row-major [m][256]
__global__ __launch_bounds__(128) void gemm_h(const float* __restrict__ bias)
{
    __shared__ __half Ash[64][72], Asl[64][72], Wsh[64][72], Wsl[64][72];
    const int m0 = blockIdx.x * 64, n0 = blockIdx.y * 64;
    const int tid = threadIdx.x;
    const int wid = tid >> 5, lane = tid & 31;
    const int g = lane >> 2, t4 = lane & 3;

    float acc[8][4];
#pragma unroll
    for (int i = 0; i < 8; i++)
#pragma unroll
        for (int j = 0; j < 4; j++) acc[i][j] = 0.f;

    gemm_core(g_xh, g_xl, g_wsh[0], g_wsl[0], Ash, Asl, Wsh, Wsl, m0, n0, tid, acc);

    const int r0 = m0 + 16 * wid + g;
    const int r1 = r0 + 8;
#pragma unroll
    for (int nb = 0; nb < 8; nb++) {
        int c0 = n0 + 8 * nb + 2 * t4;
        float bx = bias[c0], by = bias[c0 + 1];
        float v00 = acc[nb][0] + bx, v01 = acc[nb][1] + by;
        float v10 = acc[nb][2] + bx, v11 = acc[nb][3] + by;
        *(float2*)&g_h[(size_t)r0 * EE + c0] = make_float2(v00, v01);
        *(float2*)&g_h[(size_t)r1 * EE + c0] = make_float2(v10, v11);
        __half h00 = __float2half_rn(v00), h01 = __float2half_rn(v01);
        __half h10 = __float2half_rn(v10), h11 = __float2half_rn(v11);
        *(uint32_t*)&g_hh[(size_t)r0 * EE + c0] = pack_half2(h00, h01);
        *(uint32_t*)&g_hh[(size_t)r1 * EE + c0] = pack_half2(h10, h11);
        *(uint32_t*)&g_hl[(size_t)r0 * EE + c0] =
            pack_half2(__float2half_rn(v00 - __half2float(h00)),
                       __float2half_rn(v01 - __half2float(h01)));
        *(uint32_t*)&g_hl[(size_t)r1 * EE + c0] =
            pack_half2(__float2half_rn(v10 - __half2float(h10)),
                       __float2half_rn(v11 - __half2float(h11)));
    }
}

// q (z=0, scale QSCALE), k (z=1), u (z=2) in one launch.
__global__ __launch_bounds__(128) void gemm_qku(const float* __restrict__ bias_q,
                                                const float* __restrict__ bias_k,
                                                const float* __restrict__ bias_v)
{
    __shared__ __half Ash[64][72], Asl[64][72], Wsh[64][72], Wsl[64][72];
    const int m0 = blockIdx.x * 64, n0 = blockIdx.y * 64;
    const int z = blockIdx.z;
    const int tid = threadIdx.x;
    const int wid = tid >> 5, lane = tid & 31;
    const int g = lane >> 2, t4 = lane & 3;

    const __half* Wh = g_wsh[z + 1];
    const __half* Wl = g_wsl[z + 1];
    const float* bias = (z == 0) ? bias_q : (z == 1) ? bias_k : bias_v;

    float acc[8][4];
#pragma unroll
    for (int i = 0; i < 8; i++)
#pragma unroll
        for (int j = 0; j < 4; j++) acc[i][j] = 0.f;

    gemm_core(g_hh, g_hl, Wh, Wl, Ash, Asl, Wsh, Wsl, m0, n0, tid, acc);

    const int r0 = m0 + 16 * wid + g;
    if (z == 2) {
        float z0 = 0.f, z1 = 0.f;
#pragma unroll
        for (int nb = 0; nb < 8; nb++) {
            int c0 = n0 + 8 * nb + 2 * t4;
            float bx = bias[c0], by = bias[c0 + 1];
            float wx = g_weff[c0], wy = g_weff[c0 + 1];
            z0 += (acc[nb][0] + bx) * wx + (acc[nb][1] + by) * wy;
            z1 += (acc[nb][2] + bx) * wx + (acc[nb][3] + by) * wy;
        }
#pragma unroll
        for (int m = 1; m <= 2; m <<= 1) {
            z0 += __shfl_xor_sync(0xffffffffu, z0, m);
            z1 += __shfl_xor_sync(0xffffffffu, z1, m);
        }
        if (t4 == 0) {
            int hh = n0 >> 6;
            int b = r0 >> 11, t = r0 & (TT - 1);
            size_t base = (size_t)(b * HH + hh) * TT;
            g_u[base + t] = z0;
            g_u[base + t + 8] = z1;
        }
    } else {
        __half* oh = z ? g_kh : g_qh;
        __half* ol = z ? g_kl : g_ql;
        const float scale = z ? 1.0f : QSCALE;
#pragma unroll
        for (int nb = 0; nb < 8; nb++) {
            int c0 = n0 + 8 * nb + 2 * t4;
            float bx = bias[c0], by = bias[c0 + 1];
            float v00 = (acc[nb][0] + bx) * scale, v01 = (acc[nb][1] + by) * scale;
            float v10 = (acc[nb][2] + bx) * scale, v11 = (acc[nb][3] + by) * scale;
            int hh = c0 >> 6, d = c0 & 63;
            int b = r0 >> 11, t0n = r0 & (TT - 1);
            size_t base = ((size_t)((b * HH + hh) * TT)) * HD + d;
            size_t i0 = base + (size_t)t0n * HD;
            size_t i1 = base + (size_t)(t0n + 8) * HD;
            __half h00 = __float2half_rn(v00), h01 = __float2half_rn(v01);
            __half h10 = __float2half_rn(v10), h11 = __float2half_rn(v11);
            *(uint32_t*)&oh[i0] = pack_half2(h00, h01);
            *(uint32_t*)&oh[i1] = pack_half2(h10, h11);
            *(uint32_t*)&ol[i0] =
                pack_half2(__float2half_rn(v00 - __half2float(h00)),
                           __float2half_rn(v01 - __half2float(h01)));
            *(uint32_t*)&ol[i1] =
                pack_half2(__float2half_rn(v10 - __half2float(h10)),
                           __float2half_rn(v11 - __half2float(h11)));
        }
    }
}

// ---------------------------------------------------------------------------
// 64-token chunk sums of h: g_chs[b][c][d] = sum_{t in chunk} h[b][t][d]
__global__ __launch_bounds__(256) void chs_kernel()
{
    int b = blockIdx.x, c = blockIdx.y, d = threadIdx.x;
    const float* p = g_h + ((size_t)b * TT + c * 64) * EE + d;
    float s = 0.f;
#pragma unroll 8
    for (int i = 0; i < 64; i++) s += p[(size_t)i * EE];
    g_chs[b][c][d] = s;
}

// ---------------------------------------------------------------------------
// Flash attention (R11 body), S-only: z[t] = (sum p*u)/(sum p), p = 2^(q'.k).
// fp16 3-MMA hi/lo split (fp32-accurate). CTA: 128 threads (4 warps), 64 q rows.
struct AttnSmem {
    __half kh[64][72];
    __half kl[64][72];
    float u[64];
};

__global__ __launch_bounds__(128) void attn_mma()
{
    __shared__ AttnSmem sm;
    const int tid = threadIdx.x;
    const int wid = tid >> 5;
    const int lane = tid & 31;
    const int bh = blockIdx.y;
    const int qt0 = blockIdx.x * 64;
    const int b = bh >> 2, hh = bh & 3;
    const int g = lane >> 2, t4 = lane & 3;

    // ---- stage Q (hi/lo) into kh/kl, extract A-fragments ----
    {
        const uint4* Qh = (const uint4*)(g_qh + ((size_t)bh * TT + qt0) * HD);
        const uint4* Ql = (const uint4*)(g_ql + ((size_t)bh * TT + qt0) * HD);
#pragma unroll
        for (int i = tid; i < 512; i += 128) {
            int r = i >> 3, c8 = i & 7;
            *(uint4*)&sm.kh[r][c8 * 8] = Qh[i];
            *(uint4*)&sm.kl[r][c8 * 8] = Ql[i];
        }
    }
    __syncthreads();

    uint32_t qfh[4][4], qfl[4][4];
    {
        int arow = 16 * wid + (lane & 15);
        int acolsel = (lane & 16) ? 8 : 0;
#pragma unroll
        for (int kc = 0; kc < 4; kc++) {
            ldmatrix_x4(qfh[kc], smem_u32(&sm.kh[arow][kc * 16 + acolsel]));
            ldmatrix_x4(qfl[kc], smem_u32(&sm.kl[arow][kc * 16 + acolsel]));
        }
    }
    __syncthreads();

    float lacc0 = 0.f, lacc8 = 0.f, zn0 = 0.f, zn8 = 0.f;

    const int brow4 = ((lane & 16) ? 8 : 0) + (lane & 7);
    const int bsel8 = (lane & 8) ? 8 : 0;

    for (int kt = 0; kt < TT / 64; kt++) {
        // ---- load K tile (hi/lo) + u segment ----
        {
            const size_t base = ((size_t)bh * TT + kt * 64) * HD;
            const uint4* Kh = (const uint4*)(g_kh + base);
            const uint4* Kl = (const uint4*)(g_kl + base);
#pragma unroll
            for (int i = tid; i < 512; i += 128) {
                int r = i >> 3, c8 = i & 7;
                *(uint4*)&sm.kh[r][c8 * 8] = Kh[i];
                *(uint4*)&sm.kl[r][c8 * 8] = Kl[i];
            }
            if (tid < 16)
                *(float4*)&sm.u[tid * 4] =
                    *(const float4*)&g_u[(size_t)bh * TT + kt * 64 + tid * 4];
        }
        __syncthreads();

        // ---- S = Q K^T, 3-way split, x4 B-loads over nb pairs ----
        float S[8][4];
#pragma unroll
        for (int i = 0; i < 8; i++)
#pragma unroll
            for (int j = 0; j < 4; j++) S[i][j] = 0.f;
#pragma unroll
        for (int kc = 0; kc < 4; kc++) {
#pragma unroll
            for (int nbp = 0; nbp < 4; nbp++) {
                uint32_t bf4[4], bl4[4];
                ldmatrix_x4(bf4, smem_u32(&sm.kh[16 * nbp + brow4][16 * kc + bsel8]));
                ldmatrix_x4(bl4, smem_u32(&sm.kl[16 * nbp + brow4][16 * kc + bsel8]));
                mma16816(S[2 * nbp],     qfh[kc], bf4);
                mma16816(S[2 * nbp],     qfh[kc], bl4);
                mma16816(S[2 * nbp],     qfl[kc], bf4);
                mma16816(S[2 * nbp + 1], qfh[kc], bf4 + 2);
                mma16816(S[2 * nbp + 1], qfh[kc], bl4 + 2);
                mma16816(S[2 * nbp + 1], qfl[kc], bf4 + 2);
            }
        }

        // ---- p = 2^s; accumulate l and z-numerator ----
#pragma unroll
        for (int nb = 0; nb < 8; nb++) {
            float2 uu = *(const float2*)&sm.u[8 * nb + 2 * t4];
            float p0 = fexp2(S[nb][0]);
            float p1 = fexp2(S[nb][1]);
            float p2 = fexp2(S[nb][2]);
            float p3 = fexp2(S[nb][3]);
            lacc0 += p0 + p1;
            lacc8 += p2 + p3;
            zn0 += p0 * uu.x + p1 * uu.y;
            zn8 += p2 * uu.x + p3 * uu.y;
        }
        __syncthreads();
    }

    // reduce across the 4 lanes of each row group
#pragma unroll
    for (int m = 1; m <= 2; m <<= 1) {
        lacc0 += __shfl_xor_sync(0xffffffffu, lacc0, m);
        lacc8 += __shfl_xor_sync(0xffffffffu, lacc8, m);
        zn0 += __shfl_xor_sync(0xffffffffu, zn0, m);
        zn8 += __shfl_xor_sync(0xffffffffu, zn8, m);
    }
    if (t4 == 0) {
        int row = qt0 + 16 * wid + g;
        g_zp[hh][b * TT + row] = zn0 / lacc0;
        g_zp[hh][b * TT + row + 8] = zn8 / lacc8;
    }
}

// ---------------------------------------------------------------------------
// bs[t] = sigmoid(sum_h zp[h][t] + b_eff)
__global__ __launch_bounds__(256) void zsig_kernel()
{
    int t = blockIdx.x * 256 + threadIdx.x;
    float z = g_zp[0][t] + g_zp[1][t] + g_zp[2][t] + g_zp[3][t] + g_weff[EE];
    g_bs[t] = 1.0f / (1.0f + expf(-z));
}

// ---------------------------------------------------------------------------
// Per batch: fp64 cumsum -> pid -> segment means (chunk sums + edges) -> proj
__global__ __launch_bounds__(256) void finalize_kernel(const float* __restrict__ w_pr,
                                                       const float* __restrict__ b_pr,
                                                       float* __restrict__ out)
{
    __shared__ float  sc[TT];
    __shared__ double sd[TT];
    __shared__ double part[256];
    __shared__ unsigned char pids[TT];
    __shared__ int starts[PP + 1];
    __shared__ float pe[PP][EE];

    const int b = blockIdx.x;
    const int tid = threadIdx.x;

    for (int t = tid; t < TT; t += 256) sc[t] = g_bs[b * TT + t];
    __syncthreads();

    {
        double s = 0.0;
#pragma unroll
        for (int i = 0; i < 8; i++) s += (double)sc[tid * 8 + i];
        part[tid] = s;
    }
    __syncthreads();
    if (tid == 0) {
        double run = 0.0;
        for (int i = 0; i < 256; i++) { double v = part[i]; part[i] = run; run += v; }
    }
    __syncthreads();
    {
        double c = part[tid];
#pragma unroll
        for (int i = 0; i < 8; i++) { c += (double)sc[tid * 8 + i]; sd[tid * 8 + i] = c; }
    }
    __syncthreads();

    double total = sd[TT - 1];
    double inv = 1.0 / fmax(total, 1e-6);
    for (int t = tid; t < TT; t += 256) {
        int p = (int)(sd[t] * inv * (double)PP);
        pids[t] = (unsigned char)(p > PP - 1 ? PP - 1 : p);
    }
    __syncthreads();

    // parallel boundary-start detection (pids monotone non-decreasing)
    if (tid == 0) {
        int p0 = pids[0];
        for (int p = 0; p <= p0; p++) starts[p] = 0;
        int plast = pids[TT - 1];
        for (int p = plast + 1; p <= PP; p++) starts[p] = TT;
    }
    for (int t = tid + 1; t < TT; t += 256) {
        int pprev = pids[t - 1], pcur = pids[t];
        for (int p = pprev + 1; p <= pcur; p++) starts[p] = t;
    }
    __syncthreads();

    // segment means via chunk sums + edge tokens; thread owns dim d = tid
    const float* hb = g_h + (size_t)b * TT * EE;
    for (int p = 0; p < PP; p++) {
        int s0 = starts[p], s1 = starts[p + 1];
        float sum = 0.f;
        int cs = (s0 + 63) >> 6, ce = s1 >> 6;
        if (cs <= ce) {
            for (int c = cs; c < ce; c++) sum += g_chs[b][c][tid];
            for (int t = s0; t < cs * 64; t++) sum += hb[(size_t)t * EE + tid];
            for (int t = ce * 64; t < s1; t++) sum += hb[(size_t)t * EE + tid];
        } else {
            for (int t = s0; t < s1; t++) sum += hb[(size_t)t * EE + tid];
        }
        float cnt = (float)(s1 - s0);
        pe[p][tid] = sum / fmaxf(cnt, 1.0f);
    }
    __syncthreads();

    // out[b][p][n] = pe[p].w_pr[n] + b_pr[n]; thread owns n = tid
    float bn = b_pr[tid];
    const float* wrow = w_pr + (size_t)tid * EE;
    for (int p = 0; p < PP; p++) {
        float a0 = 0.f, a1 = 0.f;
#pragma unroll 8
        for (int d = 0; d < EE; d += 2) {
            a0 += pe[p][d]     * wrow[d];
            a1 += pe[p][d + 1] * wrow[d + 1];
        }
        out[(size_t)(b * PP + p) * EE + tid] = bn + a0 + a1;
    }
}

// ---------------------------------------------------------------------------
extern "C" void kernel_launch(void* const* d_in, const int* in_sizes, int n_in,
                              void* d_out, int out_size)
{
    SplitArgs sa;
    sa.x    = (const float*)d_in[0];
    sa.w_in = (const float*)d_in[1];
    const float* b_in = (const float*)d_in[2];
    sa.w_q  = (const float*)d_in[3];
    const float* b_q  = (const float*)d_in[4];
    sa.w_k  = (const float*)d_in[5];
    const float* b_k  = (const float*)d_in[6];
    sa.w_v  = (const float*)d_in[7];
    const float* b_v  = (const float*)d_in[8];
    sa.w_o  = (const float*)d_in[9];
    sa.b_o  = (const float*)d_in[10];
    sa.w_bd = (const float*)d_in[11];
    sa.b_bd = (const float*)d_in[12];
    const float* w_pr = (const float*)d_in[13];
    const float* b_pr = (const float*)d_in[14];
    float* out = (float*)d_out;

    // launch 1: all splits + weff
    split_all<<<4353, 256>>>(sa);

    // launch 2: h
    gemm_h<<<dim3(BT / 64, EE / 64), 128>>>(b_in);
    // launch 3: q + k + u fused via grid.z
    gemm_qku<<<dim3(BT / 64, EE / 64, 3), 128>>>(b_q, b_k, b_v);

    // launch 4: attention (ncu capture slot)
    attn_mma<<<dim3(TT / 64, NBH), 128>>>();

    chs_kernel<<<dim3(BB, 32), 256>>>();
    zsig_kernel<<<BT / 256, 256>>>();
    finalize_kernel<<<BB, 256>>>(w_pr, b_pr, out);
}

// round 14
// speedup vs baseline: 1.2281x; 1.0100x over previous
#include <cuda_runtime.h>
#include <cuda_fp16.h>
#include <math.h>
#include <stdint.h>

// Problem constants
#define BB   8
#define TT   2048
#define EE   256
#define HH   4
#define HD   64
#define PP   8
#define BT   (BB*TT)          // 16384
#define NBH  (BB*HH)          // 32

// q pre-scale: (1/sqrt(64)) * log2(e)  -> softmax via bare exp2
#define QSCALE 0.18033688011112042f

// ---------------- scratch (device globals; no allocation allowed) -----------
__device__ float g_h[BT*EE];
__device__ float g_bs[BT];
__device__ float g_weff[EE+1];       // w_eff[256] + b_eff
__device__ float g_zp[HH][BT];       // per-head boundary partials
__device__ float g_chs[BB][32][EE];  // 64-token chunk sums of h
__device__ float g_u[NBH*TT];        // u[bh][t] = v[bh][t] . w_eff_slice(h)
// fp16 hi/lo splits
__device__ __half g_xh[BT*EE], g_xl[BT*EE];
__device__ __half g_hh[BT*EE], g_hl[BT*EE];
__device__ __half g_wsh[4][EE*EE], g_wsl[4][EE*EE];   // w_in, w_q, w_k, w_v
// [bh][t][64] layouts
__device__ __half g_qh[NBH*TT*HD], g_ql[NBH*TT*HD];
__device__ __half g_kh[NBH*TT*HD], g_kl[NBH*TT*HD];

// ============================ warp-mma helpers ==============================
__device__ __forceinline__ uint32_t smem_u32(const void* p) {
    uint32_t a;
    asm("{ .reg .u64 tmp; cvta.to.shared.u64 tmp, %1; cvt.u32.u64 %0, tmp; }"
        : "=r"(a) : "l"(p));
    return a;
}
__device__ __forceinline__ void ldmatrix_x4(uint32_t* r, uint32_t addr) {
    asm volatile("ldmatrix.sync.aligned.m8n8.x4.shared.b16 {%0,%1,%2,%3}, [%4];"
                 : "=r"(r[0]), "=r"(r[1]), "=r"(r[2]), "=r"(r[3]) : "r"(addr));
}
__device__ __forceinline__ void mma16816(float* d, const uint32_t* a, const uint32_t* b) {
    asm volatile(
        "mma.sync.aligned.m16n8k16.row.col.f32.f16.f16.f32 "
        "{%0,%1,%2,%3}, {%4,%5,%6,%7}, {%8,%9}, {%0,%1,%2,%3};"
        : "+f"(d[0]), "+f"(d[1]), "+f"(d[2]), "+f"(d[3])
        : "r"(a[0]), "r"(a[1]), "r"(a[2]), "r"(a[3]), "r"(b[0]), "r"(b[1]));
}
__device__ __forceinline__ uint32_t pack_half2(__half lo, __half hi) {
    return (uint32_t)__half_as_ushort(lo) | ((uint32_t)__half_as_ushort(hi) << 16);
}
__device__ __forceinline__ float fexp2(float x) {
    float r;
    asm("ex2.approx.f32 %0, %1;" : "=f"(r) : "f"(x));
    return r;
}

// ---------------------------------------------------------------------------
// Fused: x/w_in/w_q/w_k/w_v fp16 hi/lo splits + weff computation.
struct SplitArgs {
    const float *x, *w_in, *w_q, *w_k, *w_v, *w_o, *w_bd, *b_o, *b_bd;
};

__device__ __forceinline__ void do_split4(const float* __restrict__ src,
                                          __half* __restrict__ dh,
                                          __half* __restrict__ dl, int i)
{
    float4 v = ((const float4*)src)[i];
    __half h0 = __float2half_rn(v.x), h1 = __float2half_rn(v.y);
    __half h2 = __float2half_rn(v.z), h3 = __float2half_rn(v.w);
    __half l0 = __float2half_rn(v.x - __half2float(h0));
    __half l1 = __float2half_rn(v.y - __half2float(h1));
    __half l2 = __float2half_rn(v.z - __half2float(h2));
    __half l3 = __float2half_rn(v.w - __half2float(h3));
    ((uint2*)dh)[i] = make_uint2(pack_half2(h0, h1), pack_half2(h2, h3));
    ((uint2*)dl)[i] = make_uint2(pack_half2(l0, l1), pack_half2(l2, l3));
}

__global__ __launch_bounds__(256) void split_all(SplitArgs a)
{
    int blk = blockIdx.x;
    int tid = threadIdx.x;
    if (blk < 4096) {
        do_split4(a.x, g_xh, g_xl, blk * 256 + tid);
    } else if (blk < 4352) {
        int w = (blk - 4096) >> 6;            // 0..3
        int i = ((blk - 4096) & 63) * 256 + tid;
        const float* src = (w == 0) ? a.w_in : (w == 1) ? a.w_q : (w == 2) ? a.w_k : a.w_v;
        do_split4(src, g_wsh[w], g_wsl[w], i);
    } else {
        int j = tid;
        float s = 0.f;
        for (int i = 0; i < EE; i++) s += a.w_bd[i] * a.w_o[i * EE + j];
        g_weff[j] = s;
        if (j == 0) {
            float bb = a.b_bd[0];
            for (int i = 0; i < EE; i++) bb += a.w_bd[i] * a.b_o[i];
            g_weff[EE] = bb;
        }
    }
}

// ---------------------------------------------------------------------------
// Shared GEMM mainloop: acc[8][4] += A[64,k] W^T tile, fp16 3-MMA split.
// CTA: 128 threads (4 warps), tile 64(m) x 64(n). x4 B-operand ldmatrix.
__device__ __forceinline__ void gemm_core(const __half* __restrict__ Ah,
                                          const __half* __restrict__ Al,
                                          const __half* __restrict__ Wh,
                                          const __half* __restrict__ Wl,
                                          __half (*Ash)[72], __half (*Asl)[72],
                                          __half (*Wsh)[72], __half (*Wsl)[72],
                                          int m0, int n0, int tid,
                                          float acc[8][4])
{
    const int wid = tid >> 5;
    const int lane = tid & 31;
    const int arow = 16 * wid + (lane & 15);
    const int asel = (lane & 16) ? 8 : 0;
    const int brow4 = ((lane & 16) ? 8 : 0) + (lane & 7);
    const int bsel8 = (lane & 8) ? 8 : 0;

    for (int kc0 = 0; kc0 < EE; kc0 += 64) {
        if (kc0) __syncthreads();
#pragma unroll
        for (int j = 0; j < 4; j++) {
            int i = tid + j * 128;            // 0..511
            int r = i >> 3, c = (i & 7) * 8;
            *(uint4*)&Ash[r][c] = *(const uint4*)&Ah[(size_t)(m0 + r) * EE + kc0 + c];
            *(uint4*)&Asl[r][c] = *(const uint4*)&Al[(size_t)(m0 + r) * EE + kc0 + c];
            *(uint4*)&Wsh[r][c] = *(const uint4*)&Wh[(size_t)(n0 + r) * EE + kc0 + c];
            *(uint4*)&Wsl[r][c] = *(const uint4*)&Wl[(size_t)(n0 + r) * EE + kc0 + c];
        }
        __syncthreads();

        uint32_t afh[4][4], afl[4][4];
#pragma unroll
        for (int kc = 0; kc < 4; kc++) {
            ldmatrix_x4(afh[kc], smem_u32(&Ash[arow][kc * 16 + asel]));
            ldmatrix_x4(afl[kc], smem_u32(&Asl[arow][kc * 16 + asel]));
        }
#pragma unroll
        for (int kc = 0; kc < 4; kc++) {
#pragma unroll
            for (int nbp = 0; nbp < 4; nbp++) {
                uint32_t bf4[4], bl4[4];
                ldmatrix_x4(bf4, smem_u32(&Wsh[16 * nbp + brow4][16 * kc + bsel8]));
                ldmatrix_x4(bl4, smem_u32(&Wsl[16 * nbp + brow4][16 * kc + bsel8]));
                mma16816(acc[2 * nbp],     afh[kc], bf4);
                mma16816(acc[2 * nbp],     afh[kc], bl4);
                mma16816(acc[2 * nbp],     afl[kc], bf4);
                mma16816(acc[2 * nbp + 1], afh[kc], bf4 + 2);
                mma16816(acc[2 * nbp + 1], afh[kc], bl4 + 2);
                mma16816(acc[2 * nbp + 1], afl[kc], bf4 + 2);
            }
        }
    }
}

// h = x @ w_in^T + b_in: fp32 out + hi/lo split, row-major [m][256]
__global__ __launch_bounds__(128) void gemm_h(const float* __restrict__ bias)
{
    __shared__ __half Ash[64][72], Asl[64][72], Wsh[64][72], Wsl[64][72];
    const int m0 = blockIdx.x * 64, n0 = blockIdx.y * 64;
    const int tid = threadIdx.x;
    const int wid = tid >> 5, lane = tid & 31;
    const int g = lane >> 2, t4 = lane & 3;

    float acc[8][4];
#pragma unroll
    for (int i = 0; i < 8; i++)
#pragma unroll
        for (int j = 0; j < 4; j++) acc[i][j] = 0.f;

    gemm_core(g_xh, g_xl, g_wsh[0], g_wsl[0], Ash, Asl, Wsh, Wsl, m0, n0, tid, acc);

    const int r0 = m0 + 16 * wid + g;
    const int r1 = r0 + 8;
#pragma unroll
    for (int nb = 0; nb < 8; nb++) {
        int c0 = n0 + 8 * nb + 2 * t4;
        float bx = bias[c0], by = bias[c0 + 1];
        float v00 = acc[nb][0] + bx, v01 = acc[nb][1] + by;
        float v10 = acc[nb][2] + bx, v11 = acc[nb][3] + by;
        *(float2*)&g_h[(size_t)r0 * EE + c0] = make_float2(v00, v01);
        *(float2*)&g_h[(size_t)r1 * EE + c0] = make_float2(v10, v11);
        __half h00 = __float2half_rn(v00), h01 = __float2half_rn(v01);
        __half h10 = __float2half_rn(v10), h11 = __float2half_rn(v11);
        *(uint32_t*)&g_hh[(size_t)r0 * EE + c0] = pack_half2(h00, h01);
        *(uint32_t*)&g_hh[(size_t)r1 * EE + c0] = pack_half2(h10, h11);
        *(uint32_t*)&g_hl[(size_t)r0 * EE + c0] =
            pack_half2(__float2half_rn(v00 - __half2float(h00)),
                       __float2half_rn(v01 - __half2float(h01)));
        *(uint32_t*)&g_hl[(size_t)r1 * EE + c0] =
            pack_half2(__float2half_rn(v10 - __half2float(h10)),
                       __float2half_rn(v11 - __half2float(h11)));
    }
}

// q (z=0, scale QSCALE), k (z=1), u (z=2) in one launch.
__global__ __launch_bounds__(128) void gemm_qku(const float* __restrict__ bias_q,
                                                const float* __restrict__ bias_k,
                                                const float* __restrict__ bias_v)
{
    __shared__ __half Ash[64][72], Asl[64][72], Wsh[64][72], Wsl[64][72];
    const int m0 = blockIdx.x * 64, n0 = blockIdx.y * 64;
    const int z = blockIdx.z;
    const int tid = threadIdx.x;
    const int wid = tid >> 5, lane = tid & 31;
    const int g = lane >> 2, t4 = lane & 3;

    const __half* Wh = g_wsh[z + 1];
    const __half* Wl = g_wsl[z + 1];
    const float* bias = (z == 0) ? bias_q : (z == 1) ? bias_k : bias_v;

    float acc[8][4];
#pragma unroll
    for (int i = 0; i < 8; i++)
#pragma unroll
        for (int j = 0; j < 4; j++) acc[i][j] = 0.f;

    gemm_core(g_hh, g_hl, Wh, Wl, Ash, Asl, Wsh, Wsl, m0, n0, tid, acc);

    const int r0 = m0 + 16 * wid + g;
    if (z == 2) {
        float z0 = 0.f, z1 = 0.f;
#pragma unroll
        for (int nb = 0; nb < 8; nb++) {
            int c0 = n0 + 8 * nb + 2 * t4;
            float bx = bias[c0], by = bias[c0 + 1];
            float wx = g_weff[c0], wy = g_weff[c0 + 1];
            z0 += (acc[nb][0] + bx) * wx + (acc[nb][1] + by) * wy;
            z1 += (acc[nb][2] + bx) * wx + (acc[nb][3] + by) * wy;
        }
#pragma unroll
        for (int m = 1; m <= 2; m <<= 1) {
            z0 += __shfl_xor_sync(0xffffffffu, z0, m);
            z1 += __shfl_xor_sync(0xffffffffu, z1, m);
        }
        if (t4 == 0) {
            int hh = n0 >> 6;
            int b = r0 >> 11, t = r0 & (TT - 1);
            size_t base = (size_t)(b * HH + hh) * TT;
            g_u[base + t] = z0;
            g_u[base + t + 8] = z1;
        }
    } else {
        __half* oh = z ? g_kh : g_qh;
        __half* ol = z ? g_kl : g_ql;
        const float scale = z ? 1.0f : QSCALE;
#pragma unroll
        for (int nb = 0; nb < 8; nb++) {
            int c0 = n0 + 8 * nb + 2 * t4;
            float bx = bias[c0], by = bias[c0 + 1];
            float v00 = (acc[nb][0] + bx) * scale, v01 = (acc[nb][1] + by) * scale;
            float v10 = (acc[nb][2] + bx) * scale, v11 = (acc[nb][3] + by) * scale;
            int hh = c0 >> 6, d = c0 & 63;
            int b = r0 >> 11, t0n = r0 & (TT - 1);
            size_t base = ((size_t)((b * HH + hh) * TT)) * HD + d;
            size_t i0 = base + (size_t)t0n * HD;
            size_t i1 = base + (size_t)(t0n + 8) * HD;
            __half h00 = __float2half_rn(v00), h01 = __float2half_rn(v01);
            __half h10 = __float2half_rn(v10), h11 = __float2half_rn(v11);
            *(uint32_t*)&oh[i0] = pack_half2(h00, h01);
            *(uint32_t*)&oh[i1] = pack_half2(h10, h11);
            *(uint32_t*)&ol[i0] =
                pack_half2(__float2half_rn(v00 - __half2float(h00)),
                           __float2half_rn(v01 - __half2float(h01)));
            *(uint32_t*)&ol[i1] =
                pack_half2(__float2half_rn(v10 - __half2float(h10)),
                           __float2half_rn(v11 - __half2float(h11)));
        }
    }
}

// ---------------------------------------------------------------------------
// 64-token chunk sums of h: g_chs[b][c][d] = sum_{t in chunk} h[b][t][d]
__global__ __launch_bounds__(256) void chs_kernel()
{
    int b = blockIdx.x, c = blockIdx.y, d = threadIdx.x;
    const float* p = g_h + ((size_t)b * TT + c * 64) * EE + d;
    float s = 0.f;
#pragma unroll 8
    for (int i = 0; i < 64; i++) s += p[(size_t)i * EE];
    g_chs[b][c][d] = s;
}

// ---------------------------------------------------------------------------
// Flash attention, S-only: z[t] = (sum p*u)/(sum p), p = 2^(q'.k).
// fp16 3-MMA hi/lo split (fp32-accurate). CTA: 128 threads (4 warps), 64 q rows.
// nbp-outer loop: each nbp's exp2 burst overlaps the next nbp's MMA burst.
struct AttnSmem {
    __half kh[64][72];
    __half kl[64][72];
    float u[64];
};

__global__ __launch_bounds__(128) void attn_mma()
{
    __shared__ AttnSmem sm;
    const int tid = threadIdx.x;
    const int wid = tid >> 5;
    const int lane = tid & 31;
    const int bh = blockIdx.y;
    const int qt0 = blockIdx.x * 64;
    const int b = bh >> 2, hh = bh & 3;
    const int g = lane >> 2, t4 = lane & 3;

    // ---- stage Q (hi/lo) into kh/kl, extract A-fragments ----
    {
        const uint4* Qh = (const uint4*)(g_qh + ((size_t)bh * TT + qt0) * HD);
        const uint4* Ql = (const uint4*)(g_ql + ((size_t)bh * TT + qt0) * HD);
#pragma unroll
        for (int i = tid; i < 512; i += 128) {
            int r = i >> 3, c8 = i & 7;
            *(uint4*)&sm.kh[r][c8 * 8] = Qh[i];
            *(uint4*)&sm.kl[r][c8 * 8] = Ql[i];
        }
    }
    __syncthreads();

    uint32_t qfh[4][4], qfl[4][4];
    {
        int arow = 16 * wid + (lane & 15);
        int acolsel = (lane & 16) ? 8 : 0;
#pragma unroll
        for (int kc = 0; kc < 4; kc++) {
            ldmatrix_x4(qfh[kc], smem_u32(&sm.kh[arow][kc * 16 + acolsel]));
            ldmatrix_x4(qfl[kc], smem_u32(&sm.kl[arow][kc * 16 + acolsel]));
        }
    }
    __syncthreads();

    float lacc0 = 0.f, lacc8 = 0.f, zn0 = 0.f, zn8 = 0.f;

    const int brow4 = ((lane & 16) ? 8 : 0) + (lane & 7);
    const int bsel8 = (lane & 8) ? 8 : 0;

    for (int kt = 0; kt < TT / 64; kt++) {
        // ---- load K tile (hi/lo) + u segment ----
        {
            const size_t base = ((size_t)bh * TT + kt * 64) * HD;
            const uint4* Kh = (const uint4*)(g_kh + base);
            const uint4* Kl = (const uint4*)(g_kl + base);
#pragma unroll
            for (int i = tid; i < 512; i += 128) {
                int r = i >> 3, c8 = i & 7;
                *(uint4*)&sm.kh[r][c8 * 8] = Kh[i];
                *(uint4*)&sm.kl[r][c8 * 8] = Kl[i];
            }
            if (tid < 16)
                *(float4*)&sm.u[tid * 4] =
                    *(const float4*)&g_u[(size_t)bh * TT + kt * 64 + tid * 4];
        }
        __syncthreads();

        // ---- per nbp: 24 MMAs then 8 exp2 (pipes overlap across nbp) ----
#pragma unroll
        for (int nbp = 0; nbp < 4; nbp++) {
            float S[2][4];
#pragma unroll
            for (int i = 0; i < 2; i++)
#pragma unroll
                for (int j = 0; j < 4; j++) S[i][j] = 0.f;
#pragma unroll
            for (int kc = 0; kc < 4; kc++) {
                uint32_t bf4[4], bl4[4];
                ldmatrix_x4(bf4, smem_u32(&sm.kh[16 * nbp + brow4][16 * kc + bsel8]));
                ldmatrix_x4(bl4, smem_u32(&sm.kl[16 * nbp + brow4][16 * kc + bsel8]));
                mma16816(S[0], qfh[kc], bf4);
                mma16816(S[0], qfh[kc], bl4);
                mma16816(S[0], qfl[kc], bf4);
                mma16816(S[1], qfh[kc], bf4 + 2);
                mma16816(S[1], qfh[kc], bl4 + 2);
                mma16816(S[1], qfl[kc], bf4 + 2);
            }
#pragma unroll
            for (int half = 0; half < 2; half++) {
                int nb = 2 * nbp + half;
                float2 uu = *(const float2*)&sm.u[8 * nb + 2 * t4];
                float p0 = fexp2(S[half][0]);
                float p1 = fexp2(S[half][1]);
                float p2 = fexp2(S[half][2]);
                float p3 = fexp2(S[half][3]);
                lacc0 += p0 + p1;
                lacc8 += p2 + p3;
                zn0 += p0 * uu.x + p1 * uu.y;
                zn8 += p2 * uu.x + p3 * uu.y;
            }
        }
        __syncthreads();
    }

    // reduce across the 4 lanes of each row group
#pragma unroll
    for (int m = 1; m <= 2; m <<= 1) {
        lacc0 += __shfl_xor_sync(0xffffffffu, lacc0, m);
        lacc8 += __shfl_xor_sync(0xffffffffu, lacc8, m);
        zn0 += __shfl_xor_sync(0xffffffffu, zn0, m);
        zn8 += __shfl_xor_sync(0xffffffffu, zn8, m);
    }
    if (t4 == 0) {
        int row = qt0 + 16 * wid + g;
        g_zp[hh][b * TT + row] = zn0 / lacc0;
        g_zp[hh][b * TT + row + 8] = zn8 / lacc8;
    }
}

// ---------------------------------------------------------------------------
// bs[t] = sigmoid(sum_h zp[h][t] + b_eff)
__global__ __launch_bounds__(256) void zsig_kernel()
{
    int t = blockIdx.x * 256 + threadIdx.x;
    float z = g_zp[0][t] + g_zp[1][t] + g_zp[2][t] + g_zp[3][t] + g_weff[EE];
    g_bs[t] = 1.0f / (1.0f + expf(-z));
}

// ---------------------------------------------------------------------------
// Per batch: fp64 cumsum -> pid -> segment means (chunk sums + edges) -> proj
__global__ __launch_bounds__(256) void finalize_kernel(const float* __restrict__ w_pr,
                                                       const float* __restrict__ b_pr,
                                                       float* __restrict__ out)
{
    __shared__ float  sc[TT];
    __shared__ double sd[TT];
    __shared__ double part[256];
    __shared__ unsigned char pids[TT];
    __shared__ int starts[PP + 1];
    __shared__ float pe[PP][EE];

    const int b = blockIdx.x;
    const int tid = threadIdx.x;

    for (int t = tid; t < TT; t += 256) sc[t] = g_bs[b * TT + t];
    __syncthreads();

    {
        double s = 0.0;
#pragma unroll
        for (int i = 0; i < 8; i++) s += (double)sc[tid * 8 + i];
        part[tid] = s;
    }
    __syncthreads();
    if (tid == 0) {
        double run = 0.0;
        for (int i = 0; i < 256; i++) { double v = part[i]; part[i] = run; run += v; }
    }
    __syncthreads();
    {
        double c = part[tid];
#pragma unroll
        for (int i = 0; i < 8; i++) { c += (double)sc[tid * 8 + i]; sd[tid * 8 + i] = c; }
    }
    __syncthreads();

    double total = sd[TT - 1];
    double inv = 1.0 / fmax(total, 1e-6);
    for (int t = tid; t < TT; t += 256) {
        int p = (int)(sd[t] * inv * (double)PP);
        pids[t] = (unsigned char)(p > PP - 1 ? PP - 1 : p);
    }
    __syncthreads();

    // parallel boundary-start detection (pids monotone non-decreasing)
    if (tid == 0) {
        int p0 = pids[0];
        for (int p = 0; p <= p0; p++) starts[p] = 0;
        int plast = pids[TT - 1];
        for (int p = plast + 1; p <= PP; p++) starts[p] = TT;
    }
    for (int t = tid + 1; t < TT; t += 256) {
        int pprev = pids[t - 1], pcur = pids[t];
        for (int p = pprev + 1; p <= pcur; p++) starts[p] = t;
    }
    __syncthreads();

    // segment means via chunk sums + edge tokens; thread owns dim d = tid
    const float* hb = g_h + (size_t)b * TT * EE;
    for (int p = 0; p < PP; p++) {
        int s0 = starts[p], s1 = starts[p + 1];
        float sum = 0.f;
        int cs = (s0 + 63) >> 6, ce = s1 >> 6;
        if (cs <= ce) {
            for (int c = cs; c < ce; c++) sum += g_chs[b][c][tid];
            for (int t = s0; t < cs * 64; t++) sum += hb[(size_t)t * EE + tid];
            for (int t = ce * 64; t < s1; t++) sum += hb[(size_t)t * EE + tid];
        } else {
            for (int t = s0; t < s1; t++) sum += hb[(size_t)t * EE + tid];
        }
        float cnt = (float)(s1 - s0);
        pe[p][tid] = sum / fmaxf(cnt, 1.0f);
    }
    __syncthreads();

    // out[b][p][n] = pe[p].w_pr[n] + b_pr[n]; thread owns n = tid
    float bn = b_pr[tid];
    const float* wrow = w_pr + (size_t)tid * EE;
    for (int p = 0; p < PP; p++) {
        float a0 = 0.f, a1 = 0.f;
#pragma unroll 8
        for (int d = 0; d < EE; d += 2) {
            a0 += pe[p][d]     * wrow[d];
            a1 += pe[p][d + 1] * wrow[d + 1];
        }
        out[(size_t)(b * PP + p) * EE + tid] = bn + a0 + a1;
    }
}

// ---------------------------------------------------------------------------
extern "C" void kernel_launch(void* const* d_in, const int* in_sizes, int n_in,
                              void* d_out, int out_size)
{
    SplitArgs sa;
    sa.x    = (const float*)d_in[0];
    sa.w_in = (const float*)d_in[1];
    const float* b_in = (const float*)d_in[2];
    sa.w_q  = (const float*)d_in[3];
    const float* b_q  = (const float*)d_in[4];
    sa.w_k  = (const float*)d_in[5];
    const float* b_k  = (const float*)d_in[6];
    sa.w_v  = (const float*)d_in[7];
    const float* b_v  = (const float*)d_in[8];
    sa.w_o  = (const float*)d_in[9];
    sa.b_o  = (const float*)d_in[10];
    sa.w_bd = (const float*)d_in[11];
    sa.b_bd = (const float*)d_in[12];
    const float* w_pr = (const float*)d_in[13];
    const float* b_pr = (const float*)d_in[14];
    float* out = (float*)d_out;

    // launch 1: all splits + weff
    split_all<<<4353, 256>>>(sa);

    // launch 2: h
    gemm_h<<<dim3(BT / 64, EE / 64), 128>>>(b_in);
    // launch 3: q + k + u fused via grid.z
    gemm_qku<<<dim3(BT / 64, EE / 64, 3), 128>>>(b_q, b_k, b_v);

    // launch 4: attention (ncu capture slot)
    attn_mma<<<dim3(TT / 64, NBH), 128>>>();

    chs_kernel<<<dim3(BB, 32), 256>>>();
    zsig_kernel<<<BT / 256, 256>>>();
    finalize_kernel<<<BB, 256>>>(w_pr, b_pr, out);
}